// round 9
// baseline (speedup 1.0000x reference)
#include <cuda_runtime.h>
#include <cstdint>

#define NN 100000
#define FF 128
#define EE 1600000
#define GG 512          // 4*FF gates
#define NOUTD 64
#define KARY 8
#define NPERMS 4
#define PARTITIONABLE 1 // JAX jax_threefry_partitionable default (>=0.4.36). Flip to 0 if rel_err is O(1).

// ------------------------- scratch (__device__ globals; no allocation) -------------------------
__device__ float d_XW[NN * (size_t)GG];     // node_feat @ w_ih^T  (100k x 512)
__device__ float d_h[NN * (size_t)FF];
__device__ float d_c[NN * (size_t)FF];
__device__ float d_hneigh[NN * (size_t)FF];
__device__ float d_WtIH[FF * GG];           // transposed w_ih: [k][j]
__device__ float d_WtHH[FF * GG];           // transposed w_hh: [k][j]
__device__ float d_bcat[GG];                // b_ih + b_hh
__device__ int d_deg[NN];
__device__ int d_off[NN + 1];
__device__ int d_cur[NN];
__device__ int d_csr[EE];
__device__ unsigned d_ubits[EE];            // (threefry_bits >> 9), 23 bits
__device__ int d_nbrT[KARY * NN];           // step-major neighbor ids
__device__ int d_len[NN];

// ------------------------- threefry2x32-20 (bit-exact vs JAX) -------------------------
__device__ __forceinline__ uint32_t rotl32(uint32_t v, int d) { return (v << d) | (v >> (32 - d)); }

__device__ __forceinline__ void threefry2x32(uint32_t k0, uint32_t k1,
                                             uint32_t x0, uint32_t x1,
                                             uint32_t& o0, uint32_t& o1) {
    uint32_t ks2 = k0 ^ k1 ^ 0x1BD11BDAu;
    x0 += k0; x1 += k1;
#define TF_R(r) { x0 += x1; x1 = rotl32(x1, r); x1 ^= x0; }
    TF_R(13) TF_R(15) TF_R(26) TF_R(6)   x0 += k1;  x1 += ks2 + 1u;
    TF_R(17) TF_R(29) TF_R(16) TF_R(24)  x0 += ks2; x1 += k0 + 2u;
    TF_R(13) TF_R(15) TF_R(26) TF_R(6)   x0 += k0;  x1 += k1 + 3u;
    TF_R(17) TF_R(29) TF_R(16) TF_R(24)  x0 += k1;  x1 += ks2 + 4u;
    TF_R(13) TF_R(15) TF_R(26) TF_R(6)   x0 += ks2; x1 += k0 + 5u;
#undef TF_R
    o0 = x0; o1 = x1;
}

// ------------------------- activation helpers -------------------------
__device__ __forceinline__ float sigf(float x) {
    return __fdividef(1.f, 1.f + __expf(-x));
}
__device__ __forceinline__ float tanhf_fast(float x) {
    float ax = fabsf(x);
    float e = __expf(-2.f * ax);
    float t = (1.f - e) * __fdividef(1.f, 1.f + e);
    return copysignf(t, x);
}

// ------------------------- setup kernels -------------------------
__global__ void zero_pre_kernel() {
    for (int i = blockIdx.x * blockDim.x + threadIdx.x; i < NN * FF; i += gridDim.x * blockDim.x) {
        d_hneigh[i] = 0.f;
        if (i < NN) d_deg[i] = 0;
    }
}

__global__ void deg_kernel(const int* __restrict__ adj) {
    int e = blockIdx.x * blockDim.x + threadIdx.x;
    if (e >= EE) return;
    atomicAdd(&d_deg[adj[2 * e]], 1);
}

__global__ void scan_kernel() {  // single block, 1024 threads: exclusive scan of deg -> off, cur
    __shared__ int sh[32];
    int tid = threadIdx.x;
    unsigned lane = tid & 31, wid = tid >> 5;
    int carry = 0;
    for (int base = 0; base < NN; base += 1024) {
        int i = base + tid;
        int v = (i < NN) ? d_deg[i] : 0;
        int x = v;
        #pragma unroll
        for (int s = 1; s < 32; s <<= 1) {
            int y = __shfl_up_sync(0xFFFFFFFFu, x, s);
            if (lane >= s) x += y;
        }
        if (lane == 31) sh[wid] = x;
        __syncthreads();
        if (wid == 0) {
            int y2 = sh[lane];
            #pragma unroll
            for (int s = 1; s < 32; s <<= 1) {
                int z = __shfl_up_sync(0xFFFFFFFFu, y2, s);
                if (lane >= s) y2 += z;
            }
            sh[lane] = y2;
        }
        __syncthreads();
        int wpre = (wid == 0) ? 0 : sh[wid - 1];
        int incl = wpre + x;
        if (i < NN) { d_off[i] = carry + incl - v; d_cur[i] = carry + incl - v; }
        int tot = sh[31];
        __syncthreads();
        carry += tot;
    }
    if (tid == 0) d_off[NN] = carry;
}

__global__ void fill_kernel(const int* __restrict__ adj) {
    int e = blockIdx.x * blockDim.x + threadIdx.x;
    if (e >= EE) return;
    int s = adj[2 * e];
    int pos = atomicAdd(&d_cur[s], 1);
    d_csr[pos] = e;
}

__global__ void trans_kernel(const float* __restrict__ w_ih, const float* __restrict__ w_hh,
                             const float* __restrict__ b_ih, const float* __restrict__ b_hh) {
    int idx = blockIdx.x * blockDim.x + threadIdx.x;
    if (idx < FF * GG) {
        int j = idx / FF, k = idx % FF;     // w is (512,128) row-major
        d_WtIH[k * GG + j] = w_ih[idx];
        d_WtHH[k * GG + j] = w_hh[idx];
    }
    if (idx < GG) d_bcat[idx] = b_ih[idx] + b_hh[idx];
}

// ------------------------- per-perm kernels -------------------------
__global__ void rng_kernel(int p) {
    int e = blockIdx.x * blockDim.x + threadIdx.x;
    if (e >= EE) return;
    // perm_key = fold_in(key(42), p) = threefry((0,42),(0,p))
    uint32_t ka, kb;
    threefry2x32(0u, 42u, 0u, (uint32_t)p, ka, kb);
    uint32_t o0, o1, bits;
#if PARTITIONABLE
    threefry2x32(ka, kb, 0u, (uint32_t)e, o0, o1);
    bits = o0 ^ o1;
#else
    const int H = EE / 2;
    if (e < H) { threefry2x32(ka, kb, (uint32_t)e, (uint32_t)(e + H), o0, o1); bits = o0; }
    else       { threefry2x32(ka, kb, (uint32_t)(e - H), (uint32_t)e, o0, o1); bits = o1; }
#endif
    d_ubits[e] = bits >> 9;   // monotone with the uniform float; ties broken by edge idx
}

__global__ void select_kernel(const int* __restrict__ adj) {
    int n = blockIdx.x * blockDim.x + threadIdx.x;
    if (n >= NN) return;
    int off = d_off[n];
    int d = d_deg[n];
    unsigned long long k8[KARY];
    int dst8[KARY];
    #pragma unroll
    for (int i = 0; i < KARY; i++) { k8[i] = ~0ull; dst8[i] = 0; }
    for (int ii = 0; ii < d; ii++) {
        int e = d_csr[off + ii];
        unsigned long long key = ((unsigned long long)d_ubits[e] << 21) | (unsigned)e;
        int dv = adj[2 * e + 1];
        if (key < k8[KARY - 1]) {
            #pragma unroll
            for (int s = 0; s < KARY; s++) {
                if (key < k8[s]) {
                    unsigned long long tk = k8[s]; k8[s] = key; key = tk;
                    int td = dst8[s]; dst8[s] = dv; dv = td;
                }
            }
        }
    }
    int ln = d < KARY ? d : KARY;
    d_len[n] = ln;
    #pragma unroll
    for (int t = 0; t < KARY; t++) d_nbrT[t * NN + n] = (t < ln) ? dst8[t] : 0;
}

__global__ void zero_hc_kernel() {
    for (int i = blockIdx.x * blockDim.x + threadIdx.x; i < NN * FF; i += gridDim.x * blockDim.x) {
        d_h[i] = 0.f; d_c[i] = 0.f;
    }
}

__global__ void accum_kernel() {
    for (int i = blockIdx.x * blockDim.x + threadIdx.x; i < NN * FF; i += gridDim.x * blockDim.x)
        d_hneigh[i] += d_c[i];
}

// ------------------------- GEMM: XW = node_feat @ w_ih^T  (M=NN, N=512, K=128) -------------------------
__global__ __launch_bounds__(512, 1) void xw_kernel(const float* __restrict__ nf) {
    __shared__ __align__(16) float As[8 * 68];
    __shared__ __align__(16) float Bs[8 * 512];
    int tid = threadIdx.x;
    int base = blockIdx.x * 64;
    int ns = tid & 15, js = tid >> 4;    // ns: 4-node slot, js: 4-col slot within 128
    float acc[4][16];
    #pragma unroll
    for (int i = 0; i < 4; i++)
        #pragma unroll
        for (int jv = 0; jv < 16; jv++) acc[i][jv] = 0.f;

    for (int kb = 0; kb < FF; kb += 8) {
        int n_l = tid >> 3, kk = tid & 7;
        int n = base + n_l;
        As[kk * 68 + n_l] = (n < NN) ? nf[(size_t)n * FF + kb + kk] : 0.f;
        const float4* Bg = (const float4*)(d_WtIH + kb * GG);
        ((float4*)Bs)[tid] = Bg[tid];
        ((float4*)Bs)[tid + 512] = Bg[tid + 512];
        __syncthreads();
        #pragma unroll
        for (int k2 = 0; k2 < 8; ++k2) {
            float4 a = *(const float4*)&As[k2 * 68 + ns * 4];
            float av[4] = {a.x, a.y, a.z, a.w};
            #pragma unroll
            for (int q = 0; q < 4; ++q) {
                float4 b = *(const float4*)&Bs[k2 * 512 + q * 128 + js * 4];
                float bv[4] = {b.x, b.y, b.z, b.w};
                #pragma unroll
                for (int i = 0; i < 4; i++)
                    #pragma unroll
                    for (int v = 0; v < 4; v++)
                        acc[i][q * 4 + v] = fmaf(av[i], bv[v], acc[i][q * 4 + v]);
            }
        }
        __syncthreads();
    }
    #pragma unroll
    for (int i = 0; i < 4; i++) {
        int n = base + ns * 4 + i;
        if (n >= NN) continue;
        #pragma unroll
        for (int q = 0; q < 4; q++) {
            float4 r = make_float4(acc[i][q * 4 + 0], acc[i][q * 4 + 1], acc[i][q * 4 + 2], acc[i][q * 4 + 3]);
            *(float4*)&d_XW[(size_t)n * GG + q * 128 + js * 4] = r;
        }
    }
}

// --------------- LSTM step: gates = XW[nbr] + bcat + h @ w_hh^T; fused cell update ---------------
__global__ __launch_bounds__(512, 1) void lstm_step_kernel(int t) {
    __shared__ __align__(16) float As[8 * 68];
    __shared__ __align__(16) float Bs[8 * 512];
    int tid = threadIdx.x;
    int base = blockIdx.x * 64;
    int ns = tid & 15, js = tid >> 4;
    float acc[4][16];

    // init: gather XW row of neighbor + combined bias (thread owns cols q*128 + js*4 + v, q=0..3)
    float4 bc[4];
    #pragma unroll
    for (int q = 0; q < 4; q++) bc[q] = *(const float4*)&d_bcat[q * 128 + js * 4];
    #pragma unroll
    for (int i = 0; i < 4; i++) {
        int n = base + ns * 4 + i;
        int nb = (n < NN) ? d_nbrT[t * NN + n] : 0;
        const float4* xr = (const float4*)&d_XW[(size_t)nb * GG];
        #pragma unroll
        for (int q = 0; q < 4; q++) {
            float4 x4 = xr[q * 32 + js];
            acc[i][q * 4 + 0] = x4.x + bc[q].x;
            acc[i][q * 4 + 1] = x4.y + bc[q].y;
            acc[i][q * 4 + 2] = x4.z + bc[q].z;
            acc[i][q * 4 + 3] = x4.w + bc[q].w;
        }
    }

    // K-loop: h-part only (K=128)
    for (int kb = 0; kb < FF; kb += 8) {
        int n_l = tid >> 3, kk = tid & 7;
        int n = base + n_l;
        As[kk * 68 + n_l] = (n < NN) ? d_h[(size_t)n * FF + kb + kk] : 0.f;
        const float4* Bg = (const float4*)(d_WtHH + kb * GG);
        ((float4*)Bs)[tid] = Bg[tid];
        ((float4*)Bs)[tid + 512] = Bg[tid + 512];
        __syncthreads();
        #pragma unroll
        for (int k2 = 0; k2 < 8; ++k2) {
            float4 a = *(const float4*)&As[k2 * 68 + ns * 4];
            float av[4] = {a.x, a.y, a.z, a.w};
            #pragma unroll
            for (int q = 0; q < 4; ++q) {
                float4 b = *(const float4*)&Bs[k2 * 512 + q * 128 + js * 4];
                float bv[4] = {b.x, b.y, b.z, b.w};
                #pragma unroll
                for (int i = 0; i < 4; i++)
                    #pragma unroll
                    for (int v = 0; v < 4; v++)
                        acc[i][q * 4 + v] = fmaf(av[i], bv[v], acc[i][q * 4 + v]);
            }
        }
        __syncthreads();
    }

    // cell epilogue: gate groups i/f/g/o are q=0..3, feature index f = js*4+v (thread-local)
    #pragma unroll
    for (int i = 0; i < 4; i++) {
        int n = base + ns * 4 + i;
        if (n >= NN) continue;
        if (t >= d_len[n]) continue;           // state frozen past sequence length
        size_t off = (size_t)n * FF + js * 4;
        float4 co = *(const float4*)&d_c[off];
        float cv[4] = {co.x, co.y, co.z, co.w};
        float cn[4], hn[4];
        #pragma unroll
        for (int v = 0; v < 4; v++) {
            float iv = sigf(acc[i][0 * 4 + v]);
            float fv = sigf(acc[i][1 * 4 + v]);
            float gv = tanhf_fast(acc[i][2 * 4 + v]);
            float ov = sigf(acc[i][3 * 4 + v]);
            float cc = fmaf(fv, cv[v], iv * gv);
            cn[v] = cc;
            hn[v] = ov * tanhf_fast(cc);
        }
        *(float4*)&d_c[off] = make_float4(cn[0], cn[1], cn[2], cn[3]);
        *(float4*)&d_h[off] = make_float4(hn[0], hn[1], hn[2], hn[3]);
    }
}

// ------------------------- output layer -------------------------
__global__ __launch_bounds__(512) void out_kernel(const float* __restrict__ nf,
                                                  const float* __restrict__ w,
                                                  const float* __restrict__ bias,
                                                  float* __restrict__ out) {
    int base = blockIdx.x * 64;
    int o = threadIdx.x & 63;
    int ng = threadIdx.x >> 6;   // 0..7
    for (int g = 0; g < 8; ++g) {
        int n = base + g * 8 + ng;
        if (n >= NN) continue;
        float z = bias[o];
        const float* nfr = nf + (size_t)n * FF;
        const float* hr = d_hneigh + (size_t)n * FF;
        #pragma unroll 4
        for (int k = 0; k < FF; k++) z = fmaf(nfr[k], w[k * NOUTD + o], z);
        #pragma unroll 4
        for (int k = 0; k < FF; k++) z = fmaf(0.25f * hr[k], w[(FF + k) * NOUTD + o], z);
        out[(size_t)n * NOUTD + o] = 1.f / (1.f + __expf(-z));
    }
}

// ------------------------- launch -------------------------
extern "C" void kernel_launch(void* const* d_in, const int* in_sizes, int n_in,
                              void* d_out, int out_size) {
    const float* node_feat = (const float*)d_in[0];
    const int*   adj       = (const int*)d_in[1];
    const float* w_ih      = (const float*)d_in[2];
    const float* w_hh      = (const float*)d_in[3];
    const float* b_ih      = (const float*)d_in[4];
    const float* b_hh      = (const float*)d_in[5];
    const float* weight    = (const float*)d_in[6];
    const float* bias      = (const float*)d_in[7];
    float* out = (float*)d_out;

    const int EB = (EE + 255) / 256;        // 6250
    const int NB64 = (NN + 63) / 64;        // 1563

    zero_pre_kernel<<<2048, 256>>>();
    deg_kernel<<<EB, 256>>>(adj);
    scan_kernel<<<1, 1024>>>();
    fill_kernel<<<EB, 256>>>(adj);
    trans_kernel<<<(FF * GG + 511) / 512, 512>>>(w_ih, w_hh, b_ih, b_hh);
    xw_kernel<<<NB64, 512>>>(node_feat);

    for (int p = 0; p < NPERMS; p++) {
        rng_kernel<<<EB, 256>>>(p);
        select_kernel<<<(NN + 255) / 256, 256>>>(adj);
        zero_hc_kernel<<<2048, 256>>>();
        for (int t = 0; t < KARY; t++) lstm_step_kernel<<<NB64, 512>>>(t);
        accum_kernel<<<2048, 256>>>();
    }
    out_kernel<<<NB64, 512>>>(node_feat, weight, bias, out);
}

// round 10
// speedup vs baseline: 1.1471x; 1.1471x over previous
#include <cuda_runtime.h>
#include <cstdint>

#define NN 100000
#define FF 128
#define EE 1600000
#define GG 512          // 4*FF gates
#define NOUTD 64
#define KARY 8
#define NPERMS 4
#define PARTITIONABLE 1

// ------------------------- packed f32x2 helpers (FFMA2 path) -------------------------
#define FMA2(d, a, b, c) asm("fma.rn.f32x2 %0, %1, %2, %3;" : "=l"(d) : "l"(a), "l"(b), "l"(c))
#define ADD2(d, a, b)    asm("add.rn.f32x2 %0, %1, %2;"     : "=l"(d) : "l"(a), "l"(b))
#define PACK2(out, lo, hi)  asm("mov.b64 %0, {%1, %2};" : "=l"(out) : "f"(lo), "f"(hi))
#define UNPACK2(lo, hi, in) asm("mov.b64 {%0, %1}, %2;" : "=f"(lo), "=f"(hi) : "l"(in))

// ------------------------- scratch (__device__ globals; no allocation) -------------------------
__device__ float d_XW[NN * (size_t)GG];     // node_feat @ w_ih^T  (100k x 512)
__device__ float d_h[NN * (size_t)FF];
__device__ float d_c[NN * (size_t)FF];
__device__ float d_hneigh[NN * (size_t)FF];
__device__ float d_WtIH[FF * GG];           // transposed w_ih: [k][j]
__device__ float d_WtHH[FF * GG];           // transposed w_hh: [k][j]
__device__ float d_bcat[GG];                // b_ih + b_hh
__device__ int d_deg[NN];
__device__ int d_off[NN + 1];
__device__ int d_cur[NN];
__device__ int d_csr[EE];
__device__ unsigned d_ubits[EE];            // (threefry_bits >> 9), 23 bits
__device__ int d_nbrT[KARY * NN];           // step-major neighbor ids
__device__ int d_len[NN];

// ------------------------- threefry2x32-20 (bit-exact vs JAX) -------------------------
__device__ __forceinline__ uint32_t rotl32(uint32_t v, int d) { return (v << d) | (v >> (32 - d)); }

__device__ __forceinline__ void threefry2x32(uint32_t k0, uint32_t k1,
                                             uint32_t x0, uint32_t x1,
                                             uint32_t& o0, uint32_t& o1) {
    uint32_t ks2 = k0 ^ k1 ^ 0x1BD11BDAu;
    x0 += k0; x1 += k1;
#define TF_R(r) { x0 += x1; x1 = rotl32(x1, r); x1 ^= x0; }
    TF_R(13) TF_R(15) TF_R(26) TF_R(6)   x0 += k1;  x1 += ks2 + 1u;
    TF_R(17) TF_R(29) TF_R(16) TF_R(24)  x0 += ks2; x1 += k0 + 2u;
    TF_R(13) TF_R(15) TF_R(26) TF_R(6)   x0 += k0;  x1 += k1 + 3u;
    TF_R(17) TF_R(29) TF_R(16) TF_R(24)  x0 += k1;  x1 += ks2 + 4u;
    TF_R(13) TF_R(15) TF_R(26) TF_R(6)   x0 += ks2; x1 += k0 + 5u;
#undef TF_R
    o0 = x0; o1 = x1;
}

// ------------------------- activation helpers -------------------------
__device__ __forceinline__ float sigf(float x) {
    return __fdividef(1.f, 1.f + __expf(-x));
}
__device__ __forceinline__ float tanhf_fast(float x) {
    float ax = fabsf(x);
    float e = __expf(-2.f * ax);
    float t = (1.f - e) * __fdividef(1.f, 1.f + e);
    return copysignf(t, x);
}

// ------------------------- setup kernels -------------------------
__global__ void zero_pre_kernel() {
    for (int i = blockIdx.x * blockDim.x + threadIdx.x; i < NN * FF; i += gridDim.x * blockDim.x) {
        d_hneigh[i] = 0.f;
        if (i < NN) d_deg[i] = 0;
    }
}

__global__ void deg_kernel(const int* __restrict__ adj) {
    int e = blockIdx.x * blockDim.x + threadIdx.x;
    if (e >= EE) return;
    atomicAdd(&d_deg[adj[2 * e]], 1);
}

__global__ void scan_kernel() {  // single block, 1024 threads: exclusive scan of deg -> off, cur
    __shared__ int sh[32];
    int tid = threadIdx.x;
    unsigned lane = tid & 31, wid = tid >> 5;
    int carry = 0;
    for (int base = 0; base < NN; base += 1024) {
        int i = base + tid;
        int v = (i < NN) ? d_deg[i] : 0;
        int x = v;
        #pragma unroll
        for (int s = 1; s < 32; s <<= 1) {
            int y = __shfl_up_sync(0xFFFFFFFFu, x, s);
            if (lane >= s) x += y;
        }
        if (lane == 31) sh[wid] = x;
        __syncthreads();
        if (wid == 0) {
            int y2 = sh[lane];
            #pragma unroll
            for (int s = 1; s < 32; s <<= 1) {
                int z = __shfl_up_sync(0xFFFFFFFFu, y2, s);
                if (lane >= s) y2 += z;
            }
            sh[lane] = y2;
        }
        __syncthreads();
        int wpre = (wid == 0) ? 0 : sh[wid - 1];
        int incl = wpre + x;
        if (i < NN) { d_off[i] = carry + incl - v; d_cur[i] = carry + incl - v; }
        int tot = sh[31];
        __syncthreads();
        carry += tot;
    }
    if (tid == 0) d_off[NN] = carry;
}

__global__ void fill_kernel(const int* __restrict__ adj) {
    int e = blockIdx.x * blockDim.x + threadIdx.x;
    if (e >= EE) return;
    int s = adj[2 * e];
    int pos = atomicAdd(&d_cur[s], 1);
    d_csr[pos] = e;
}

__global__ void trans_kernel(const float* __restrict__ w_ih, const float* __restrict__ w_hh,
                             const float* __restrict__ b_ih, const float* __restrict__ b_hh) {
    int idx = blockIdx.x * blockDim.x + threadIdx.x;
    if (idx < FF * GG) {
        int j = idx / FF, k = idx % FF;     // w is (512,128) row-major
        d_WtIH[k * GG + j] = w_ih[idx];
        d_WtHH[k * GG + j] = w_hh[idx];
    }
    if (idx < GG) d_bcat[idx] = b_ih[idx] + b_hh[idx];
}

// ------------------------- per-perm kernels -------------------------
__global__ void rng_kernel(int p) {
    int e = blockIdx.x * blockDim.x + threadIdx.x;
    if (e >= EE) return;
    uint32_t ka, kb;
    threefry2x32(0u, 42u, 0u, (uint32_t)p, ka, kb);
    uint32_t o0, o1, bits;
#if PARTITIONABLE
    threefry2x32(ka, kb, 0u, (uint32_t)e, o0, o1);
    bits = o0 ^ o1;
#else
    const int H = EE / 2;
    if (e < H) { threefry2x32(ka, kb, (uint32_t)e, (uint32_t)(e + H), o0, o1); bits = o0; }
    else       { threefry2x32(ka, kb, (uint32_t)(e - H), (uint32_t)e, o0, o1); bits = o1; }
#endif
    d_ubits[e] = bits >> 9;   // monotone with the uniform float; ties broken by edge idx
}

__global__ void select_kernel(const int* __restrict__ adj) {
    int n = blockIdx.x * blockDim.x + threadIdx.x;
    if (n >= NN) return;
    int off = d_off[n];
    int d = d_deg[n];
    unsigned long long k8[KARY];
    int dst8[KARY];
    #pragma unroll
    for (int i = 0; i < KARY; i++) { k8[i] = ~0ull; dst8[i] = 0; }
    for (int ii = 0; ii < d; ii++) {
        int e = d_csr[off + ii];
        unsigned long long key = ((unsigned long long)d_ubits[e] << 21) | (unsigned)e;
        int dv = adj[2 * e + 1];
        if (key < k8[KARY - 1]) {
            #pragma unroll
            for (int s = 0; s < KARY; s++) {
                if (key < k8[s]) {
                    unsigned long long tk = k8[s]; k8[s] = key; key = tk;
                    int td = dst8[s]; dst8[s] = dv; dv = td;
                }
            }
        }
    }
    int ln = d < KARY ? d : KARY;
    d_len[n] = ln;
    #pragma unroll
    for (int t = 0; t < KARY; t++) d_nbrT[t * NN + n] = (t < ln) ? dst8[t] : 0;
}

__global__ void accum_kernel() {
    for (int i = blockIdx.x * blockDim.x + threadIdx.x; i < NN * FF; i += gridDim.x * blockDim.x)
        d_hneigh[i] += d_c[i];
}

// ------------------------- GEMM: XW = node_feat @ w_ih^T  (M=NN, N=512, K=128) -------------------------
__global__ __launch_bounds__(512, 1) void xw_kernel(const float* __restrict__ nf) {
    __shared__ __align__(16) float As[8 * 68];
    __shared__ __align__(16) float Bs[8 * 512];
    int tid = threadIdx.x;
    int base = blockIdx.x * 64;
    int ns = tid & 15, js = tid >> 4;    // ns: 4-node slot, js: 4-col slot within 128
    unsigned long long acc2[4][8];       // [node][gate*2 + pair] packed f32x2
    #pragma unroll
    for (int i = 0; i < 4; i++)
        #pragma unroll
        for (int jv = 0; jv < 8; jv++) acc2[i][jv] = 0ull;

    for (int kb = 0; kb < FF; kb += 8) {
        int n_l = tid >> 3, kk = tid & 7;
        int n = base + n_l;
        As[kk * 68 + n_l] = (n < NN) ? nf[(size_t)n * FF + kb + kk] : 0.f;
        const float4* Bg = (const float4*)(d_WtIH + kb * GG);
        ((float4*)Bs)[tid] = Bg[tid];
        ((float4*)Bs)[tid + 512] = Bg[tid + 512];
        __syncthreads();
        #pragma unroll
        for (int k2 = 0; k2 < 8; ++k2) {
            float4 a = *(const float4*)&As[k2 * 68 + ns * 4];
            unsigned long long ap[4];
            PACK2(ap[0], a.x, a.x); PACK2(ap[1], a.y, a.y);
            PACK2(ap[2], a.z, a.z); PACK2(ap[3], a.w, a.w);
            #pragma unroll
            for (int q = 0; q < 4; ++q) {
                ulonglong2 b2 = *(const ulonglong2*)&Bs[k2 * 512 + q * 128 + js * 4];
                #pragma unroll
                for (int i = 0; i < 4; i++) {
                    FMA2(acc2[i][q * 2 + 0], ap[i], b2.x, acc2[i][q * 2 + 0]);
                    FMA2(acc2[i][q * 2 + 1], ap[i], b2.y, acc2[i][q * 2 + 1]);
                }
            }
        }
        __syncthreads();
    }
    #pragma unroll
    for (int i = 0; i < 4; i++) {
        int n = base + ns * 4 + i;
        if (n >= NN) continue;
        #pragma unroll
        for (int q = 0; q < 4; q++) {
            ulonglong2 r;
            r.x = acc2[i][q * 2 + 0];
            r.y = acc2[i][q * 2 + 1];
            *(ulonglong2*)&d_XW[(size_t)n * GG + q * 128 + js * 4] = r;
        }
    }
}

// ------------------- LSTM step t=0: h=c=0 -> no GEMM; gates = XW[nbr0] + bcat -------------------
__global__ void lstm_step0_kernel() {
    int idx = blockIdx.x * blockDim.x + threadIdx.x;   // NN*32 threads, 4 features each
    if (idx >= NN * 32) return;
    int n = idx >> 5, fs = (idx & 31) * 4;
    bool act = d_len[n] > 0;
    int nb = act ? d_nbrT[n] : 0;
    const float* xr = d_XW + (size_t)nb * GG;
    float cn[4], hn[4];
    #pragma unroll
    for (int v = 0; v < 4; v++) {
        int f = fs + v;
        float iv = sigf(xr[0 * 128 + f] + d_bcat[0 * 128 + f]);
        float gv = tanhf_fast(xr[2 * 128 + f] + d_bcat[2 * 128 + f]);
        float ov = sigf(xr[3 * 128 + f] + d_bcat[3 * 128 + f]);
        float cc = iv * gv;
        cn[v] = act ? cc : 0.f;
        hn[v] = act ? ov * tanhf_fast(cc) : 0.f;
    }
    size_t off = (size_t)n * FF + fs;
    *(float4*)&d_c[off] = make_float4(cn[0], cn[1], cn[2], cn[3]);
    *(float4*)&d_h[off] = make_float4(hn[0], hn[1], hn[2], hn[3]);
}

// --------------- LSTM step t>=1: gates = XW[nbr] + bcat + h @ w_hh^T; fused cell update ---------------
__global__ __launch_bounds__(512, 1) void lstm_step_kernel(int t) {
    __shared__ __align__(16) float As[8 * 68];
    __shared__ __align__(16) float Bs[8 * 512];
    int tid = threadIdx.x;
    int base = blockIdx.x * 64;
    int ns = tid & 15, js = tid >> 4;
    unsigned long long acc2[4][8];

    // init: gather XW row of neighbor + combined bias (packed pairs)
    unsigned long long bp[8];
    #pragma unroll
    for (int q = 0; q < 4; q++) {
        ulonglong2 bq = *(const ulonglong2*)&d_bcat[q * 128 + js * 4];
        bp[q * 2 + 0] = bq.x; bp[q * 2 + 1] = bq.y;
    }
    #pragma unroll
    for (int i = 0; i < 4; i++) {
        int n = base + ns * 4 + i;
        int nb = (n < NN) ? d_nbrT[t * NN + n] : 0;
        const float* xr = d_XW + (size_t)nb * GG;
        #pragma unroll
        for (int q = 0; q < 4; q++) {
            ulonglong2 x2 = *(const ulonglong2*)&xr[q * 128 + js * 4];
            ADD2(acc2[i][q * 2 + 0], x2.x, bp[q * 2 + 0]);
            ADD2(acc2[i][q * 2 + 1], x2.y, bp[q * 2 + 1]);
        }
    }

    // K-loop: h-part only (K=128)
    for (int kb = 0; kb < FF; kb += 8) {
        int n_l = tid >> 3, kk = tid & 7;
        int n = base + n_l;
        As[kk * 68 + n_l] = (n < NN) ? d_h[(size_t)n * FF + kb + kk] : 0.f;
        const float4* Bg = (const float4*)(d_WtHH + kb * GG);
        ((float4*)Bs)[tid] = Bg[tid];
        ((float4*)Bs)[tid + 512] = Bg[tid + 512];
        __syncthreads();
        #pragma unroll
        for (int k2 = 0; k2 < 8; ++k2) {
            float4 a = *(const float4*)&As[k2 * 68 + ns * 4];
            unsigned long long ap[4];
            PACK2(ap[0], a.x, a.x); PACK2(ap[1], a.y, a.y);
            PACK2(ap[2], a.z, a.z); PACK2(ap[3], a.w, a.w);
            #pragma unroll
            for (int q = 0; q < 4; ++q) {
                ulonglong2 b2 = *(const ulonglong2*)&Bs[k2 * 512 + q * 128 + js * 4];
                #pragma unroll
                for (int i = 0; i < 4; i++) {
                    FMA2(acc2[i][q * 2 + 0], ap[i], b2.x, acc2[i][q * 2 + 0]);
                    FMA2(acc2[i][q * 2 + 1], ap[i], b2.y, acc2[i][q * 2 + 1]);
                }
            }
        }
        __syncthreads();
    }

    // cell epilogue: gate groups i/f/g/o are q=0..3, feature index f = js*4+v (thread-local)
    #pragma unroll
    for (int i = 0; i < 4; i++) {
        int n = base + ns * 4 + i;
        if (n >= NN) continue;
        if (t >= d_len[n]) continue;           // state frozen past sequence length
        float gv4[4][4];
        #pragma unroll
        for (int q = 0; q < 4; q++) {
            UNPACK2(gv4[q][0], gv4[q][1], acc2[i][q * 2 + 0]);
            UNPACK2(gv4[q][2], gv4[q][3], acc2[i][q * 2 + 1]);
        }
        size_t off = (size_t)n * FF + js * 4;
        float4 co = *(const float4*)&d_c[off];
        float cv[4] = {co.x, co.y, co.z, co.w};
        float cn[4], hn[4];
        #pragma unroll
        for (int v = 0; v < 4; v++) {
            float iv = sigf(gv4[0][v]);
            float fv = sigf(gv4[1][v]);
            float gv = tanhf_fast(gv4[2][v]);
            float ov = sigf(gv4[3][v]);
            float cc = fmaf(fv, cv[v], iv * gv);
            cn[v] = cc;
            hn[v] = ov * tanhf_fast(cc);
        }
        *(float4*)&d_c[off] = make_float4(cn[0], cn[1], cn[2], cn[3]);
        *(float4*)&d_h[off] = make_float4(hn[0], hn[1], hn[2], hn[3]);
    }
}

// ------------------------- output layer -------------------------
__global__ __launch_bounds__(512) void out_kernel(const float* __restrict__ nf,
                                                  const float* __restrict__ w,
                                                  const float* __restrict__ bias,
                                                  float* __restrict__ out) {
    int base = blockIdx.x * 64;
    int o = threadIdx.x & 63;
    int ng = threadIdx.x >> 6;   // 0..7
    for (int g = 0; g < 8; ++g) {
        int n = base + g * 8 + ng;
        if (n >= NN) continue;
        float z = bias[o];
        const float* nfr = nf + (size_t)n * FF;
        const float* hr = d_hneigh + (size_t)n * FF;
        #pragma unroll 4
        for (int k = 0; k < FF; k++) z = fmaf(nfr[k], w[k * NOUTD + o], z);
        #pragma unroll 4
        for (int k = 0; k < FF; k++) z = fmaf(0.25f * hr[k], w[(FF + k) * NOUTD + o], z);
        out[(size_t)n * NOUTD + o] = 1.f / (1.f + __expf(-z));
    }
}

// ------------------------- launch -------------------------
extern "C" void kernel_launch(void* const* d_in, const int* in_sizes, int n_in,
                              void* d_out, int out_size) {
    const float* node_feat = (const float*)d_in[0];
    const int*   adj       = (const int*)d_in[1];
    const float* w_ih      = (const float*)d_in[2];
    const float* w_hh      = (const float*)d_in[3];
    const float* b_ih      = (const float*)d_in[4];
    const float* b_hh      = (const float*)d_in[5];
    const float* weight    = (const float*)d_in[6];
    const float* bias      = (const float*)d_in[7];
    float* out = (float*)d_out;

    const int EB = (EE + 255) / 256;        // 6250
    const int NB64 = (NN + 63) / 64;        // 1563

    zero_pre_kernel<<<2048, 256>>>();
    deg_kernel<<<EB, 256>>>(adj);
    scan_kernel<<<1, 1024>>>();
    fill_kernel<<<EB, 256>>>(adj);
    trans_kernel<<<(FF * GG + 511) / 512, 512>>>(w_ih, w_hh, b_ih, b_hh);
    xw_kernel<<<NB64, 512>>>(node_feat);

    for (int p = 0; p < NPERMS; p++) {
        rng_kernel<<<EB, 256>>>(p);
        select_kernel<<<(NN + 255) / 256, 256>>>(adj);
        lstm_step0_kernel<<<(NN * 32 + 255) / 256, 256>>>();
        for (int t = 1; t < KARY; t++) lstm_step_kernel<<<NB64, 512>>>(t);
        accum_kernel<<<2048, 256>>>();
    }
    out_kernel<<<NB64, 512>>>(node_feat, weight, bias, out);
}

// round 14
// speedup vs baseline: 1.6154x; 1.4083x over previous
#include <cuda_runtime.h>
#include <cstdint>

#define NN 100000
#define FF 128
#define EE 1600000
#define GG 512          // 4*FF gates
#define NOUTD 64
#define KARY 8
#define NPERMS 4
#define PARTITIONABLE 1
#define TILE 128
#define NTILES ((NN + TILE - 1) / TILE)   // 782

// ---- packed f32x2 helpers (xw_kernel) ----
#define FMA2(d, a, b, c) asm("fma.rn.f32x2 %0, %1, %2, %3;" : "=l"(d) : "l"(a), "l"(b), "l"(c))
#define PACK2(out, lo, hi)  asm("mov.b64 %0, {%1, %2};" : "=l"(out) : "f"(lo), "f"(hi))

// ------------------------- scratch -------------------------
__device__ float d_XW[NN * (size_t)GG];
__device__ float d_hneigh[NN * (size_t)FF];
__device__ float d_WtIH[FF * GG];
__device__ float d_bcat[GG];
__device__ uint32_t d_Bpack[GG * FF];       // Whh tf32, mma-fragment-packed, 4 chunks of 16384
__device__ int d_deg[NN];
__device__ int d_off[NN + 1];
__device__ int d_cur[NN];
__device__ int d_csr[EE];
__device__ unsigned d_ubits[EE];
__device__ int d_nbrT[KARY * NN];
__device__ int d_len[NN];

// ------------------------- mma.sync helpers (sm_80+ baseline; works on sm_103) -------------------------
__device__ __forceinline__ uint32_t smem_u32(const void* p) {
    uint32_t a;
    asm("{ .reg .u64 t; cvta.to.shared.u64 t, %1; cvt.u32.u64 %0, t; }" : "=r"(a) : "l"(p));
    return a;
}
__device__ __forceinline__ uint32_t f2tf32(float v) {
    uint32_t u;
    asm("cvt.rna.tf32.f32 %0, %1;" : "=r"(u) : "f"(v));
    return u;
}
#define MMA4(d, a, bb0, bb1) asm volatile( \
    "mma.sync.aligned.m16n8k8.row.col.f32.tf32.tf32.f32 {%0,%1,%2,%3}, {%4,%5,%6,%7}, {%8,%9}, {%0,%1,%2,%3};" \
    : "+f"((d)[0]), "+f"((d)[1]), "+f"((d)[2]), "+f"((d)[3]) \
    : "r"((a).x), "r"((a).y), "r"((a).z), "r"((a).w), "r"(bb0), "r"(bb1))

__device__ __forceinline__ void cp16(uint32_t s, const void* g) {
    asm volatile("cp.async.cg.shared.global [%0], [%1], 16;" :: "r"(s), "l"(g));
}
#define CP_COMMIT() asm volatile("cp.async.commit_group;")
#define CP_WAIT(N)  asm volatile("cp.async.wait_group %0;" :: "n"(N))

// ------------------------- threefry2x32-20 -------------------------
__device__ __forceinline__ uint32_t rotl32(uint32_t v, int d) { return (v << d) | (v >> (32 - d)); }
__device__ __forceinline__ void threefry2x32(uint32_t k0, uint32_t k1,
                                             uint32_t x0, uint32_t x1,
                                             uint32_t& o0, uint32_t& o1) {
    uint32_t ks2 = k0 ^ k1 ^ 0x1BD11BDAu;
    x0 += k0; x1 += k1;
#define TF_R(r) { x0 += x1; x1 = rotl32(x1, r); x1 ^= x0; }
    TF_R(13) TF_R(15) TF_R(26) TF_R(6)   x0 += k1;  x1 += ks2 + 1u;
    TF_R(17) TF_R(29) TF_R(16) TF_R(24)  x0 += ks2; x1 += k0 + 2u;
    TF_R(13) TF_R(15) TF_R(26) TF_R(6)   x0 += k0;  x1 += k1 + 3u;
    TF_R(17) TF_R(29) TF_R(16) TF_R(24)  x0 += k1;  x1 += ks2 + 4u;
    TF_R(13) TF_R(15) TF_R(26) TF_R(6)   x0 += ks2; x1 += k0 + 5u;
#undef TF_R
    o0 = x0; o1 = x1;
}

__device__ __forceinline__ float sigf(float x) { return __fdividef(1.f, 1.f + __expf(-x)); }
__device__ __forceinline__ float tanhf_fast(float x) {
    float ax = fabsf(x);
    float e = __expf(-2.f * ax);
    float t = (1.f - e) * __fdividef(1.f, 1.f + e);
    return copysignf(t, x);
}

// ------------------------- setup kernels -------------------------
__global__ void zero_pre_kernel() {
    for (int i = blockIdx.x * blockDim.x + threadIdx.x; i < NN * FF; i += gridDim.x * blockDim.x) {
        d_hneigh[i] = 0.f;
        if (i < NN) d_deg[i] = 0;
    }
}

__global__ void deg_kernel(const int* __restrict__ adj) {
    int e = blockIdx.x * blockDim.x + threadIdx.x;
    if (e >= EE) return;
    atomicAdd(&d_deg[adj[2 * e]], 1);
}

__global__ void scan_kernel() {
    __shared__ int sh[32];
    int tid = threadIdx.x;
    unsigned lane = tid & 31, wid = tid >> 5;
    int carry = 0;
    for (int base = 0; base < NN; base += 1024) {
        int i = base + tid;
        int v = (i < NN) ? d_deg[i] : 0;
        int x = v;
        #pragma unroll
        for (int s = 1; s < 32; s <<= 1) {
            int y = __shfl_up_sync(0xFFFFFFFFu, x, s);
            if (lane >= s) x += y;
        }
        if (lane == 31) sh[wid] = x;
        __syncthreads();
        if (wid == 0) {
            int y2 = sh[lane];
            #pragma unroll
            for (int s = 1; s < 32; s <<= 1) {
                int z = __shfl_up_sync(0xFFFFFFFFu, y2, s);
                if (lane >= s) y2 += z;
            }
            sh[lane] = y2;
        }
        __syncthreads();
        int wpre = (wid == 0) ? 0 : sh[wid - 1];
        int incl = wpre + x;
        if (i < NN) { d_off[i] = carry + incl - v; d_cur[i] = carry + incl - v; }
        int tot = sh[31];
        __syncthreads();
        carry += tot;
    }
    if (tid == 0) d_off[NN] = carry;
}

__global__ void fill_kernel(const int* __restrict__ adj) {
    int e = blockIdx.x * blockDim.x + threadIdx.x;
    if (e >= EE) return;
    int s = adj[2 * e];
    int pos = atomicAdd(&d_cur[s], 1);
    d_csr[pos] = e;
}

__global__ void trans_kernel(const float* __restrict__ w_ih,
                             const float* __restrict__ b_ih, const float* __restrict__ b_hh) {
    int idx = blockIdx.x * blockDim.x + threadIdx.x;
    if (idx < FF * GG) {
        int j = idx / FF, k = idx % FF;
        d_WtIH[k * GG + j] = w_ih[idx];
    }
    if (idx < GG) d_bcat[idx] = b_ih[idx] + b_hh[idx];
}

// Whh (512,128) -> tf32 mma B fragments:
// e = c*16384 + i*1024 + wn*256 + lane*8 + nt*2 + br
// value = tf32(Whh[c*128 + wn*32 + nt*8 + lane/4][i*8 + lane%4 + br*4])
__global__ void bpack_kernel(const float* __restrict__ w_hh) {
    int e = blockIdx.x * blockDim.x + threadIdx.x;
    if (e >= GG * FF) return;
    int br = e & 1, nt = (e >> 1) & 3, lane = (e >> 3) & 31;
    int wn = (e >> 8) & 3, i = (e >> 10) & 15, c = e >> 14;
    int gate = c * 128 + wn * 32 + nt * 8 + (lane >> 2);
    int k = i * 8 + (lane & 3) + br * 4;
    d_Bpack[e] = f2tf32(w_hh[gate * FF + k]);
}

// ------------------------- per-perm kernels -------------------------
__global__ void rng_kernel(int p) {
    int e = blockIdx.x * blockDim.x + threadIdx.x;
    if (e >= EE) return;
    uint32_t ka, kb;
    threefry2x32(0u, 42u, 0u, (uint32_t)p, ka, kb);
    uint32_t o0, o1, bits;
#if PARTITIONABLE
    threefry2x32(ka, kb, 0u, (uint32_t)e, o0, o1);
    bits = o0 ^ o1;
#else
    const int H = EE / 2;
    if (e < H) { threefry2x32(ka, kb, (uint32_t)e, (uint32_t)(e + H), o0, o1); bits = o0; }
    else       { threefry2x32(ka, kb, (uint32_t)(e - H), (uint32_t)e, o0, o1); bits = o1; }
#endif
    d_ubits[e] = bits >> 9;
}

__global__ void select_kernel(const int* __restrict__ adj) {
    int n = blockIdx.x * blockDim.x + threadIdx.x;
    if (n >= NN) return;
    int off = d_off[n];
    int d = d_deg[n];
    unsigned long long k8[KARY];
    int dst8[KARY];
    #pragma unroll
    for (int i = 0; i < KARY; i++) { k8[i] = ~0ull; dst8[i] = 0; }
    for (int ii = 0; ii < d; ii++) {
        int e = d_csr[off + ii];
        unsigned long long key = ((unsigned long long)d_ubits[e] << 21) | (unsigned)e;
        int dv = adj[2 * e + 1];
        if (key < k8[KARY - 1]) {
            #pragma unroll
            for (int s = 0; s < KARY; s++) {
                if (key < k8[s]) {
                    unsigned long long tk = k8[s]; k8[s] = key; key = tk;
                    int td = dst8[s]; dst8[s] = dv; dv = td;
                }
            }
        }
    }
    int ln = d < KARY ? d : KARY;
    d_len[n] = ln;
    #pragma unroll
    for (int t = 0; t < KARY; t++) d_nbrT[t * NN + n] = (t < ln) ? dst8[t] : 0;
}

// ------------------------- GEMM: XW = node_feat @ w_ih^T (fp32 FFMA2) -------------------------
__global__ __launch_bounds__(512, 1) void xw_kernel(const float* __restrict__ nf) {
    __shared__ __align__(16) float As[8 * 68];
    __shared__ __align__(16) float Bs[8 * 512];
    int tid = threadIdx.x;
    int base = blockIdx.x * 64;
    int ns = tid & 15, js = tid >> 4;
    unsigned long long acc2[4][8];
    #pragma unroll
    for (int i = 0; i < 4; i++)
        #pragma unroll
        for (int jv = 0; jv < 8; jv++) acc2[i][jv] = 0ull;

    for (int kb = 0; kb < FF; kb += 8) {
        int n_l = tid >> 3, kk = tid & 7;
        int n = base + n_l;
        As[kk * 68 + n_l] = (n < NN) ? nf[(size_t)n * FF + kb + kk] : 0.f;
        const float4* Bg = (const float4*)(d_WtIH + kb * GG);
        ((float4*)Bs)[tid] = Bg[tid];
        ((float4*)Bs)[tid + 512] = Bg[tid + 512];
        __syncthreads();
        #pragma unroll
        for (int k2 = 0; k2 < 8; ++k2) {
            float4 a = *(const float4*)&As[k2 * 68 + ns * 4];
            unsigned long long ap[4];
            PACK2(ap[0], a.x, a.x); PACK2(ap[1], a.y, a.y);
            PACK2(ap[2], a.z, a.z); PACK2(ap[3], a.w, a.w);
            #pragma unroll
            for (int q = 0; q < 4; ++q) {
                ulonglong2 b2 = *(const ulonglong2*)&Bs[k2 * 512 + q * 128 + js * 4];
                #pragma unroll
                for (int i = 0; i < 4; i++) {
                    FMA2(acc2[i][q * 2 + 0], ap[i], b2.x, acc2[i][q * 2 + 0]);
                    FMA2(acc2[i][q * 2 + 1], ap[i], b2.y, acc2[i][q * 2 + 1]);
                }
            }
        }
        __syncthreads();
    }
    #pragma unroll
    for (int i = 0; i < 4; i++) {
        int n = base + ns * 4 + i;
        if (n >= NN) continue;
        #pragma unroll
        for (int q = 0; q < 4; q++) {
            ulonglong2 r;
            r.x = acc2[i][q * 2 + 0];
            r.y = acc2[i][q * 2 + 1];
            *(ulonglong2*)&d_XW[(size_t)n * GG + q * 128 + js * 4] = r;
        }
    }
}

// ---- persistent per-tile LSTM: all 8 steps, mma.sync tf32 recurrent GEMM ----
// 256 threads = 8 warps, grid (wm 0..1) x (wn 0..3). Warp: M=64 (4 m16 tiles), N=32 (4 n8 tiles).
// SMEM: A-pack (h, tf32 frags) 64KB | B buf0 64KB | B buf1 64KB.
// c and sig(i) live in registers (fragment ownership identical across gate-group chunks).
__global__ __launch_bounds__(256, 1) void lstm_perm_kernel() {
    extern __shared__ __align__(16) uint32_t smw[];
    uint32_t sbase = smem_u32(smw);
    const int tid = threadIdx.x, lane = tid & 31, w = tid >> 5;
    const int wm = w >> 2, wn = w & 3;
    const int base = blockIdx.x * TILE;
    const int qb = 2 * (lane & 3);           // feat pair base within n-tile

    int glen[8];
    #pragma unroll
    for (int mt = 0; mt < 4; mt++)
        #pragma unroll
        for (int s = 0; s < 2; s++) {
            int g = base + wm * 64 + mt * 16 + (lane >> 2) + s * 8;
            glen[mt * 2 + s] = (g < NN) ? d_len[g] : 0;
        }

    float c_[64], sigi[64];
    #pragma unroll
    for (int i = 0; i < 64; i++) c_[i] = 0.f;

    for (int i = tid; i < 16384; i += 256) smw[i] = 0u;   // zero A-pack (h=0)
    __syncthreads();

    for (int t = 0; t < KARY; t++) {
        int nb[8];
        #pragma unroll
        for (int e = 0; e < 8; e++) {
            int g = base + wm * 64 + (e >> 1) * 16 + (lane >> 2) + (e & 1) * 8;
            nb[e] = (g < NN) ? d_nbrT[t * NN + g] : 0;
        }

        if (t > 0) {   // prefetch chunk 0 -> buf0
            const uint4* src = (const uint4*)(d_Bpack);
            uint32_t dst = sbase + 16384u * 4u;
            #pragma unroll
            for (int it = 0; it < 16; it++)
                cp16(dst + (uint32_t)(it * 256 + tid) * 16u, src + it * 256 + tid);
            CP_COMMIT();
        }

        #pragma unroll
        for (int c = 0; c < 4; c++) {
            float acc[64];
            #pragma unroll
            for (int i = 0; i < 64; i++) acc[i] = 0.f;

            if (t > 0) {
                if (c < 3) {
                    const uint4* src = (const uint4*)(d_Bpack + (c + 1) * 16384);
                    uint32_t dst = sbase + (16384u + (uint32_t)(((c + 1) & 1)) * 16384u) * 4u;
                    #pragma unroll
                    for (int it = 0; it < 16; it++)
                        cp16(dst + (uint32_t)(it * 256 + tid) * 16u, src + it * 256 + tid);
                    CP_COMMIT();
                    CP_WAIT(1);
                } else {
                    CP_WAIT(0);
                }
                __syncthreads();
                const uint32_t* Bb = smw + 16384 + (c & 1) * 16384;
                #pragma unroll 4
                for (int i = 0; i < 16; i++) {
                    uint4 a[4];
                    #pragma unroll
                    for (int mt = 0; mt < 4; mt++)
                        a[mt] = *(const uint4*)(smw + (((wm * 4 + mt) * 16 + i) * 32 + lane) * 4);
                    const uint32_t* bp = Bb + ((i * 4 + wn) * 32 + lane) * 8;
                    uint4 b0 = *(const uint4*)bp;
                    uint4 b1 = *(const uint4*)(bp + 4);
                    #pragma unroll
                    for (int mt = 0; mt < 4; mt++) {
                        MMA4(&acc[mt * 16 + 0],  a[mt], b0.x, b0.y);
                        MMA4(&acc[mt * 16 + 4],  a[mt], b0.z, b0.w);
                        MMA4(&acc[mt * 16 + 8],  a[mt], b1.x, b1.y);
                        MMA4(&acc[mt * 16 + 12], a[mt], b1.z, b1.w);
                    }
                }
            }

            // RACE FIX: chunk 3's epilogue overwrites the A-pack (h) that other
            // warps' chunk-3 mma loops are still reading. Barrier between the
            // last A-pack read and the h store.
            if (t > 0 && c == 3) __syncthreads();

            // ---- epilogue for gate-group c ----
            float2 bv[4];
            #pragma unroll
            for (int nt = 0; nt < 4; nt++)
                bv[nt] = *(const float2*)&d_bcat[c * 128 + wn * 32 + nt * 8 + qb];
            #pragma unroll
            for (int mt = 0; mt < 4; mt++)
                #pragma unroll
                for (int s = 0; s < 2; s++) {
                    int e = mt * 2 + s;
                    bool act = (t < glen[e]);
                    const float* xr = d_XW + (size_t)nb[e] * GG + c * 128 + wn * 32;
                    #pragma unroll
                    for (int nt = 0; nt < 4; nt++) {
                        float2 xv = *(const float2*)&xr[nt * 8 + qb];
                        int i0 = mt * 16 + nt * 4 + s * 2;
                        float p0 = acc[i0] + xv.x + bv[nt].x;
                        float p1 = acc[i0 + 1] + xv.y + bv[nt].y;
                        if (c == 0) {
                            sigi[i0] = sigf(p0);
                            sigi[i0 + 1] = sigf(p1);
                        } else if (c == 1) {
                            if (act) { c_[i0] *= sigf(p0); c_[i0 + 1] *= sigf(p1); }
                        } else if (c == 2) {
                            if (act) {
                                c_[i0]     = fmaf(sigi[i0],     tanhf_fast(p0), c_[i0]);
                                c_[i0 + 1] = fmaf(sigi[i0 + 1], tanhf_fast(p1), c_[i0 + 1]);
                            }
                        } else {
                            if (act) {
                                float h0 = sigf(p0) * tanhf_fast(c_[i0]);
                                float h1 = sigf(p1) * tanhf_fast(c_[i0 + 1]);
                                // store h into A-pack fragment layout (tf32)
                                #pragma unroll
                                for (int u = 0; u < 2; u++) {
                                    int qq = qb + u;
                                    int addr = (((wm * 4 + mt) * 16 + (wn * 4 + nt)) * 32
                                                + (lane >> 2) * 4 + (qq & 3)) * 4
                                               + s + 2 * (qq >> 2);
                                    smw[addr] = f2tf32(u == 0 ? h0 : h1);
                                }
                            }
                        }
                    }
                }
            if (t > 0) __syncthreads();
        }
    }

    // ---- writeback: hneigh += c (disjoint ownership, no atomics) ----
    #pragma unroll
    for (int mt = 0; mt < 4; mt++)
        #pragma unroll
        for (int s = 0; s < 2; s++) {
            int g = base + wm * 64 + mt * 16 + (lane >> 2) + s * 8;
            if (g >= NN) continue;
            #pragma unroll
            for (int nt = 0; nt < 4; nt++) {
                int i0 = mt * 16 + nt * 4 + s * 2;
                float2* hp = (float2*)&d_hneigh[(size_t)g * FF + wn * 32 + nt * 8 + qb];
                float2 v = *hp;
                v.x += c_[i0];
                v.y += c_[i0 + 1];
                *hp = v;
            }
        }
}

// ------------------------- output layer -------------------------
__global__ __launch_bounds__(512) void out_kernel(const float* __restrict__ nf,
                                                  const float* __restrict__ w,
                                                  const float* __restrict__ bias,
                                                  float* __restrict__ out) {
    int base = blockIdx.x * 64;
    int o = threadIdx.x & 63;
    int ng = threadIdx.x >> 6;
    for (int g = 0; g < 8; ++g) {
        int n = base + g * 8 + ng;
        if (n >= NN) continue;
        float z = bias[o];
        const float* nfr = nf + (size_t)n * FF;
        const float* hr = d_hneigh + (size_t)n * FF;
        #pragma unroll 4
        for (int k = 0; k < FF; k++) z = fmaf(nfr[k], w[k * NOUTD + o], z);
        #pragma unroll 4
        for (int k = 0; k < FF; k++) z = fmaf(0.25f * hr[k], w[(FF + k) * NOUTD + o], z);
        out[(size_t)n * NOUTD + o] = 1.f / (1.f + __expf(-z));
    }
}

// ------------------------- launch -------------------------
extern "C" void kernel_launch(void* const* d_in, const int* in_sizes, int n_in,
                              void* d_out, int out_size) {
    const float* node_feat = (const float*)d_in[0];
    const int*   adj       = (const int*)d_in[1];
    const float* w_ih      = (const float*)d_in[2];
    const float* w_hh      = (const float*)d_in[3];
    const float* b_ih      = (const float*)d_in[4];
    const float* b_hh      = (const float*)d_in[5];
    const float* weight    = (const float*)d_in[6];
    const float* bias      = (const float*)d_in[7];
    float* out = (float*)d_out;

    const int EB = (EE + 255) / 256;
    const int NB64 = (NN + 63) / 64;
    const int SMEM_LSTM = 3 * 65536;   // A-pack + 2 B buffers

    cudaFuncSetAttribute(lstm_perm_kernel, cudaFuncAttributeMaxDynamicSharedMemorySize, SMEM_LSTM);

    zero_pre_kernel<<<2048, 256>>>();
    deg_kernel<<<EB, 256>>>(adj);
    scan_kernel<<<1, 1024>>>();
    fill_kernel<<<EB, 256>>>(adj);
    trans_kernel<<<(FF * GG + 511) / 512, 512>>>(w_ih, b_ih, b_hh);
    bpack_kernel<<<(GG * FF + 255) / 256, 256>>>(w_hh);
    xw_kernel<<<NB64, 512>>>(node_feat);

    for (int p = 0; p < NPERMS; p++) {
        rng_kernel<<<EB, 256>>>(p);
        select_kernel<<<(NN + 255) / 256, 256>>>(adj);
        lstm_perm_kernel<<<NTILES, 256, SMEM_LSTM>>>();
    }
    out_kernel<<<NB64, 512>>>(node_feat, weight, bias, out);
}

// round 15
// speedup vs baseline: 2.1384x; 1.3237x over previous
#include <cuda_runtime.h>
#include <cstdint>

#define NN 100000
#define FF 128
#define EE 1600000
#define GG 512          // 4*FF gates
#define NOUTD 64
#define KARY 8
#define NPERMS 4
#define PARTITIONABLE 1
#define TILE 128
#define NTILES ((NN + TILE - 1) / TILE)   // 782
#define LTHREADS 512

// ---- packed f32x2 helpers (xw_kernel) ----
#define FMA2(d, a, b, c) asm("fma.rn.f32x2 %0, %1, %2, %3;" : "=l"(d) : "l"(a), "l"(b), "l"(c))
#define PACK2(out, lo, hi)  asm("mov.b64 %0, {%1, %2};" : "=l"(out) : "f"(lo), "f"(hi))

// ------------------------- scratch -------------------------
__device__ float d_XW[NN * (size_t)GG];
__device__ float d_hneigh[NN * (size_t)FF];
__device__ float d_WtIH[FF * GG];
__device__ float d_bcat[GG];
__device__ uint32_t d_Bpack[GG * FF];       // Whh tf32, mma-fragment-packed, 4 chunks of 16384
__device__ int d_deg[NN];
__device__ int d_off[NN + 1];
__device__ int d_cur[NN];
__device__ int d_csr[EE];
__device__ unsigned d_ubits[EE];
__device__ int d_nbrT[KARY * NN];
__device__ int d_len[NN];

// ------------------------- mma.sync helpers (sm_80+ baseline; works on sm_103) -------------------------
__device__ __forceinline__ uint32_t smem_u32(const void* p) {
    uint32_t a;
    asm("{ .reg .u64 t; cvta.to.shared.u64 t, %1; cvt.u32.u64 %0, t; }" : "=r"(a) : "l"(p));
    return a;
}
__device__ __forceinline__ uint32_t f2tf32(float v) {
    uint32_t u;
    asm("cvt.rna.tf32.f32 %0, %1;" : "=r"(u) : "f"(v));
    return u;
}
#define MMA4(d, a, bb0, bb1) asm volatile( \
    "mma.sync.aligned.m16n8k8.row.col.f32.tf32.tf32.f32 {%0,%1,%2,%3}, {%4,%5,%6,%7}, {%8,%9}, {%0,%1,%2,%3};" \
    : "+f"((d)[0]), "+f"((d)[1]), "+f"((d)[2]), "+f"((d)[3]) \
    : "r"((a).x), "r"((a).y), "r"((a).z), "r"((a).w), "r"(bb0), "r"(bb1))

__device__ __forceinline__ void cp16(uint32_t s, const void* g) {
    asm volatile("cp.async.cg.shared.global [%0], [%1], 16;" :: "r"(s), "l"(g));
}
#define CP_COMMIT() asm volatile("cp.async.commit_group;")
#define CP_WAIT(N)  asm volatile("cp.async.wait_group %0;" :: "n"(N))

// ------------------------- threefry2x32-20 -------------------------
__device__ __forceinline__ uint32_t rotl32(uint32_t v, int d) { return (v << d) | (v >> (32 - d)); }
__device__ __forceinline__ void threefry2x32(uint32_t k0, uint32_t k1,
                                             uint32_t x0, uint32_t x1,
                                             uint32_t& o0, uint32_t& o1) {
    uint32_t ks2 = k0 ^ k1 ^ 0x1BD11BDAu;
    x0 += k0; x1 += k1;
#define TF_R(r) { x0 += x1; x1 = rotl32(x1, r); x1 ^= x0; }
    TF_R(13) TF_R(15) TF_R(26) TF_R(6)   x0 += k1;  x1 += ks2 + 1u;
    TF_R(17) TF_R(29) TF_R(16) TF_R(24)  x0 += ks2; x1 += k0 + 2u;
    TF_R(13) TF_R(15) TF_R(26) TF_R(6)   x0 += k0;  x1 += k1 + 3u;
    TF_R(17) TF_R(29) TF_R(16) TF_R(24)  x0 += k1;  x1 += ks2 + 4u;
    TF_R(13) TF_R(15) TF_R(26) TF_R(6)   x0 += ks2; x1 += k0 + 5u;
#undef TF_R
    o0 = x0; o1 = x1;
}

__device__ __forceinline__ float sigf(float x) { return __fdividef(1.f, 1.f + __expf(-x)); }
__device__ __forceinline__ float tanhf_fast(float x) {
    float ax = fabsf(x);
    float e = __expf(-2.f * ax);
    float t = (1.f - e) * __fdividef(1.f, 1.f + e);
    return copysignf(t, x);
}

// ------------------------- setup kernels -------------------------
__global__ void zero_pre_kernel() {
    for (int i = blockIdx.x * blockDim.x + threadIdx.x; i < NN * FF; i += gridDim.x * blockDim.x) {
        d_hneigh[i] = 0.f;
        if (i < NN) d_deg[i] = 0;
    }
}

__global__ void deg_kernel(const int* __restrict__ adj) {
    int e = blockIdx.x * blockDim.x + threadIdx.x;
    if (e >= EE) return;
    atomicAdd(&d_deg[adj[2 * e]], 1);
}

__global__ void scan_kernel() {
    __shared__ int sh[32];
    int tid = threadIdx.x;
    unsigned lane = tid & 31, wid = tid >> 5;
    int carry = 0;
    for (int base = 0; base < NN; base += 1024) {
        int i = base + tid;
        int v = (i < NN) ? d_deg[i] : 0;
        int x = v;
        #pragma unroll
        for (int s = 1; s < 32; s <<= 1) {
            int y = __shfl_up_sync(0xFFFFFFFFu, x, s);
            if (lane >= s) x += y;
        }
        if (lane == 31) sh[wid] = x;
        __syncthreads();
        if (wid == 0) {
            int y2 = sh[lane];
            #pragma unroll
            for (int s = 1; s < 32; s <<= 1) {
                int z = __shfl_up_sync(0xFFFFFFFFu, y2, s);
                if (lane >= s) y2 += z;
            }
            sh[lane] = y2;
        }
        __syncthreads();
        int wpre = (wid == 0) ? 0 : sh[wid - 1];
        int incl = wpre + x;
        if (i < NN) { d_off[i] = carry + incl - v; d_cur[i] = carry + incl - v; }
        int tot = sh[31];
        __syncthreads();
        carry += tot;
    }
    if (tid == 0) d_off[NN] = carry;
}

__global__ void fill_kernel(const int* __restrict__ adj) {
    int e = blockIdx.x * blockDim.x + threadIdx.x;
    if (e >= EE) return;
    int s = adj[2 * e];
    int pos = atomicAdd(&d_cur[s], 1);
    d_csr[pos] = e;
}

__global__ void trans_kernel(const float* __restrict__ w_ih,
                             const float* __restrict__ b_ih, const float* __restrict__ b_hh) {
    int idx = blockIdx.x * blockDim.x + threadIdx.x;
    if (idx < FF * GG) {
        int j = idx / FF, k = idx % FF;
        d_WtIH[k * GG + j] = w_ih[idx];
    }
    if (idx < GG) d_bcat[idx] = b_ih[idx] + b_hh[idx];
}

// Whh (512,128) -> tf32 mma B fragments:
// e = c*16384 + i*1024 + wn*256 + lane*8 + nt*2 + br
// value = tf32(Whh[c*128 + wn*32 + nt*8 + lane/4][i*8 + lane%4 + br*4])
__global__ void bpack_kernel(const float* __restrict__ w_hh) {
    int e = blockIdx.x * blockDim.x + threadIdx.x;
    if (e >= GG * FF) return;
    int br = e & 1, nt = (e >> 1) & 3, lane = (e >> 3) & 31;
    int wn = (e >> 8) & 3, i = (e >> 10) & 15, c = e >> 14;
    int gate = c * 128 + wn * 32 + nt * 8 + (lane >> 2);
    int k = i * 8 + (lane & 3) + br * 4;
    d_Bpack[e] = f2tf32(w_hh[gate * FF + k]);
}

// ------------------------- per-perm kernels -------------------------
__global__ void rng_kernel(int p) {
    int e = blockIdx.x * blockDim.x + threadIdx.x;
    if (e >= EE) return;
    uint32_t ka, kb;
    threefry2x32(0u, 42u, 0u, (uint32_t)p, ka, kb);
    uint32_t o0, o1, bits;
#if PARTITIONABLE
    threefry2x32(ka, kb, 0u, (uint32_t)e, o0, o1);
    bits = o0 ^ o1;
#else
    const int H = EE / 2;
    if (e < H) { threefry2x32(ka, kb, (uint32_t)e, (uint32_t)(e + H), o0, o1); bits = o0; }
    else       { threefry2x32(ka, kb, (uint32_t)(e - H), (uint32_t)e, o0, o1); bits = o1; }
#endif
    d_ubits[e] = bits >> 9;
}

__global__ void select_kernel(const int* __restrict__ adj) {
    int n = blockIdx.x * blockDim.x + threadIdx.x;
    if (n >= NN) return;
    int off = d_off[n];
    int d = d_deg[n];
    unsigned long long k8[KARY];
    int dst8[KARY];
    #pragma unroll
    for (int i = 0; i < KARY; i++) { k8[i] = ~0ull; dst8[i] = 0; }
    for (int ii = 0; ii < d; ii++) {
        int e = d_csr[off + ii];
        unsigned long long key = ((unsigned long long)d_ubits[e] << 21) | (unsigned)e;
        int dv = adj[2 * e + 1];
        if (key < k8[KARY - 1]) {
            #pragma unroll
            for (int s = 0; s < KARY; s++) {
                if (key < k8[s]) {
                    unsigned long long tk = k8[s]; k8[s] = key; key = tk;
                    int td = dst8[s]; dst8[s] = dv; dv = td;
                }
            }
        }
    }
    int ln = d < KARY ? d : KARY;
    d_len[n] = ln;
    #pragma unroll
    for (int t = 0; t < KARY; t++) d_nbrT[t * NN + n] = (t < ln) ? dst8[t] : 0;
}

// ------------------------- GEMM: XW = node_feat @ w_ih^T (fp32 FFMA2) -------------------------
__global__ __launch_bounds__(512, 1) void xw_kernel(const float* __restrict__ nf) {
    __shared__ __align__(16) float As[8 * 68];
    __shared__ __align__(16) float Bs[8 * 512];
    int tid = threadIdx.x;
    int base = blockIdx.x * 64;
    int ns = tid & 15, js = tid >> 4;
    unsigned long long acc2[4][8];
    #pragma unroll
    for (int i = 0; i < 4; i++)
        #pragma unroll
        for (int jv = 0; jv < 8; jv++) acc2[i][jv] = 0ull;

    for (int kb = 0; kb < FF; kb += 8) {
        int n_l = tid >> 3, kk = tid & 7;
        int n = base + n_l;
        As[kk * 68 + n_l] = (n < NN) ? nf[(size_t)n * FF + kb + kk] : 0.f;
        const float4* Bg = (const float4*)(d_WtIH + kb * GG);
        ((float4*)Bs)[tid] = Bg[tid];
        ((float4*)Bs)[tid + 512] = Bg[tid + 512];
        __syncthreads();
        #pragma unroll
        for (int k2 = 0; k2 < 8; ++k2) {
            float4 a = *(const float4*)&As[k2 * 68 + ns * 4];
            unsigned long long ap[4];
            PACK2(ap[0], a.x, a.x); PACK2(ap[1], a.y, a.y);
            PACK2(ap[2], a.z, a.z); PACK2(ap[3], a.w, a.w);
            #pragma unroll
            for (int q = 0; q < 4; ++q) {
                ulonglong2 b2 = *(const ulonglong2*)&Bs[k2 * 512 + q * 128 + js * 4];
                #pragma unroll
                for (int i = 0; i < 4; i++) {
                    FMA2(acc2[i][q * 2 + 0], ap[i], b2.x, acc2[i][q * 2 + 0]);
                    FMA2(acc2[i][q * 2 + 1], ap[i], b2.y, acc2[i][q * 2 + 1]);
                }
            }
        }
        __syncthreads();
    }
    #pragma unroll
    for (int i = 0; i < 4; i++) {
        int n = base + ns * 4 + i;
        if (n >= NN) continue;
        #pragma unroll
        for (int q = 0; q < 4; q++) {
            ulonglong2 r;
            r.x = acc2[i][q * 2 + 0];
            r.y = acc2[i][q * 2 + 1];
            *(ulonglong2*)&d_XW[(size_t)n * GG + q * 128 + js * 4] = r;
        }
    }
}

// ---- persistent per-tile LSTM: all 8 steps, mma.sync tf32 recurrent GEMM ----
// 512 threads = 16 warps: wm 0..3 (M=32: 2 m16 tiles) x wn 0..3 (N=32: 4 n8 tiles).
// acc[32]+c_[32]+sigi[32] per thread -> no register spill (the R14 bottleneck).
// SMEM: A-pack (h, tf32 frags) 64KB | B buf0 64KB | B buf1 64KB.
__global__ __launch_bounds__(LTHREADS, 1) void lstm_perm_kernel() {
    extern __shared__ __align__(16) uint32_t smw[];
    uint32_t sbase = smem_u32(smw);
    const int tid = threadIdx.x, lane = tid & 31, w = tid >> 5;
    const int wm = w >> 2, wn = w & 3;
    const int base = blockIdx.x * TILE;
    const int qb = 2 * (lane & 3);           // feat pair base within n-tile

    int glen[4];
    #pragma unroll
    for (int mt = 0; mt < 2; mt++)
        #pragma unroll
        for (int s = 0; s < 2; s++) {
            int g = base + wm * 32 + mt * 16 + (lane >> 2) + s * 8;
            glen[mt * 2 + s] = (g < NN) ? d_len[g] : 0;
        }

    float c_[32], sigi[32];
    #pragma unroll
    for (int i = 0; i < 32; i++) c_[i] = 0.f;

    for (int i = tid; i < 16384; i += LTHREADS) smw[i] = 0u;   // zero A-pack (h=0)
    __syncthreads();

    for (int t = 0; t < KARY; t++) {
        int nb[4];
        #pragma unroll
        for (int e = 0; e < 4; e++) {
            int g = base + wm * 32 + (e >> 1) * 16 + (lane >> 2) + (e & 1) * 8;
            nb[e] = (g < NN) ? d_nbrT[t * NN + g] : 0;
        }

        if (t > 0) {   // prefetch chunk 0 -> buf0
            const uint4* src = (const uint4*)(d_Bpack);
            uint32_t dst = sbase + 16384u * 4u;
            #pragma unroll
            for (int it = 0; it < 8; it++)
                cp16(dst + (uint32_t)(it * LTHREADS + tid) * 16u, src + it * LTHREADS + tid);
            CP_COMMIT();
        }

        #pragma unroll
        for (int c = 0; c < 4; c++) {
            float acc[32];
            #pragma unroll
            for (int i = 0; i < 32; i++) acc[i] = 0.f;

            if (t > 0) {
                if (c < 3) {
                    const uint4* src = (const uint4*)(d_Bpack + (c + 1) * 16384);
                    uint32_t dst = sbase + (16384u + (uint32_t)(((c + 1) & 1)) * 16384u) * 4u;
                    #pragma unroll
                    for (int it = 0; it < 8; it++)
                        cp16(dst + (uint32_t)(it * LTHREADS + tid) * 16u, src + it * LTHREADS + tid);
                    CP_COMMIT();
                    CP_WAIT(1);
                } else {
                    CP_WAIT(0);
                }
                __syncthreads();
                const uint32_t* Bb = smw + 16384 + (c & 1) * 16384;
                #pragma unroll 4
                for (int i = 0; i < 16; i++) {
                    uint4 a[2];
                    #pragma unroll
                    for (int mt = 0; mt < 2; mt++)
                        a[mt] = *(const uint4*)(smw + (((wm * 2 + mt) * 16 + i) * 32 + lane) * 4);
                    const uint32_t* bp = Bb + ((i * 4 + wn) * 32 + lane) * 8;
                    uint4 b0 = *(const uint4*)bp;
                    uint4 b1 = *(const uint4*)(bp + 4);
                    #pragma unroll
                    for (int mt = 0; mt < 2; mt++) {
                        MMA4(&acc[mt * 16 + 0],  a[mt], b0.x, b0.y);
                        MMA4(&acc[mt * 16 + 4],  a[mt], b0.z, b0.w);
                        MMA4(&acc[mt * 16 + 8],  a[mt], b1.x, b1.y);
                        MMA4(&acc[mt * 16 + 12], a[mt], b1.z, b1.w);
                    }
                }
            }

            // RACE FIX: chunk 3's epilogue overwrites the A-pack (h) that other
            // warps' chunk-3 mma loops are still reading.
            if (t > 0 && c == 3) __syncthreads();

            // ---- epilogue for gate-group c ----
            float2 bv[4];
            #pragma unroll
            for (int nt = 0; nt < 4; nt++)
                bv[nt] = *(const float2*)&d_bcat[c * 128 + wn * 32 + nt * 8 + qb];
            #pragma unroll
            for (int mt = 0; mt < 2; mt++)
                #pragma unroll
                for (int s = 0; s < 2; s++) {
                    int e = mt * 2 + s;
                    bool act = (t < glen[e]);
                    const float* xr = d_XW + (size_t)nb[e] * GG + c * 128 + wn * 32;
                    #pragma unroll
                    for (int nt = 0; nt < 4; nt++) {
                        float2 xv = *(const float2*)&xr[nt * 8 + qb];
                        int i0 = mt * 16 + nt * 4 + s * 2;
                        float p0 = acc[i0] + xv.x + bv[nt].x;
                        float p1 = acc[i0 + 1] + xv.y + bv[nt].y;
                        if (c == 0) {
                            sigi[i0] = sigf(p0);
                            sigi[i0 + 1] = sigf(p1);
                        } else if (c == 1) {
                            if (act) { c_[i0] *= sigf(p0); c_[i0 + 1] *= sigf(p1); }
                        } else if (c == 2) {
                            if (act) {
                                c_[i0]     = fmaf(sigi[i0],     tanhf_fast(p0), c_[i0]);
                                c_[i0 + 1] = fmaf(sigi[i0 + 1], tanhf_fast(p1), c_[i0 + 1]);
                            }
                        } else {
                            if (act) {
                                float h0 = sigf(p0) * tanhf_fast(c_[i0]);
                                float h1 = sigf(p1) * tanhf_fast(c_[i0 + 1]);
                                // store h into A-pack fragment layout (tf32)
                                #pragma unroll
                                for (int u = 0; u < 2; u++) {
                                    int qq = qb + u;
                                    int addr = (((wm * 2 + mt) * 16 + (wn * 4 + nt)) * 32
                                                + (lane >> 2) * 4 + (qq & 3)) * 4
                                               + s + 2 * (qq >> 2);
                                    smw[addr] = f2tf32(u == 0 ? h0 : h1);
                                }
                            }
                        }
                    }
                }
            if (t > 0) __syncthreads();
        }
    }

    // ---- writeback: hneigh += c (disjoint ownership, no atomics) ----
    #pragma unroll
    for (int mt = 0; mt < 2; mt++)
        #pragma unroll
        for (int s = 0; s < 2; s++) {
            int g = base + wm * 32 + mt * 16 + (lane >> 2) + s * 8;
            if (g >= NN) continue;
            #pragma unroll
            for (int nt = 0; nt < 4; nt++) {
                int i0 = mt * 16 + nt * 4 + s * 2;
                float2* hp = (float2*)&d_hneigh[(size_t)g * FF + wn * 32 + nt * 8 + qb];
                float2 v = *hp;
                v.x += c_[i0];
                v.y += c_[i0 + 1];
                *hp = v;
            }
        }
}

// ------------------------- output layer -------------------------
__global__ __launch_bounds__(512) void out_kernel(const float* __restrict__ nf,
                                                  const float* __restrict__ w,
                                                  const float* __restrict__ bias,
                                                  float* __restrict__ out) {
    int base = blockIdx.x * 64;
    int o = threadIdx.x & 63;
    int ng = threadIdx.x >> 6;
    for (int g = 0; g < 8; ++g) {
        int n = base + g * 8 + ng;
        if (n >= NN) continue;
        float z = bias[o];
        const float* nfr = nf + (size_t)n * FF;
        const float* hr = d_hneigh + (size_t)n * FF;
        #pragma unroll 4
        for (int k = 0; k < FF; k++) z = fmaf(nfr[k], w[k * NOUTD + o], z);
        #pragma unroll 4
        for (int k = 0; k < FF; k++) z = fmaf(0.25f * hr[k], w[(FF + k) * NOUTD + o], z);
        out[(size_t)n * NOUTD + o] = 1.f / (1.f + __expf(-z));
    }
}

// ------------------------- launch -------------------------
extern "C" void kernel_launch(void* const* d_in, const int* in_sizes, int n_in,
                              void* d_out, int out_size) {
    const float* node_feat = (const float*)d_in[0];
    const int*   adj       = (const int*)d_in[1];
    const float* w_ih      = (const float*)d_in[2];
    const float* w_hh      = (const float*)d_in[3];
    const float* b_ih      = (const float*)d_in[4];
    const float* b_hh      = (const float*)d_in[5];
    const float* weight    = (const float*)d_in[6];
    const float* bias      = (const float*)d_in[7];
    float* out = (float*)d_out;

    const int EB = (EE + 255) / 256;
    const int NB64 = (NN + 63) / 64;
    const int SMEM_LSTM = 3 * 65536;   // A-pack + 2 B buffers

    cudaFuncSetAttribute(lstm_perm_kernel, cudaFuncAttributeMaxDynamicSharedMemorySize, SMEM_LSTM);

    zero_pre_kernel<<<2048, 256>>>();
    deg_kernel<<<EB, 256>>>(adj);
    scan_kernel<<<1, 1024>>>();
    fill_kernel<<<EB, 256>>>(adj);
    trans_kernel<<<(FF * GG + 511) / 512, 512>>>(w_ih, b_ih, b_hh);
    bpack_kernel<<<(GG * FF + 255) / 256, 256>>>(w_hh);
    xw_kernel<<<NB64, 512>>>(node_feat);

    for (int p = 0; p < NPERMS; p++) {
        rng_kernel<<<EB, 256>>>(p);
        select_kernel<<<(NN + 255) / 256, 256>>>(adj);
        lstm_perm_kernel<<<NTILES, LTHREADS, SMEM_LSTM>>>();
    }
    out_kernel<<<NB64, 512>>>(node_feat, weight, bias, out);
}

// round 16
// speedup vs baseline: 2.8688x; 1.3416x over previous
#include <cuda_runtime.h>
#include <cstdint>

#define NN 100000
#define FF 128
#define EE 1600000
#define GG 512          // 4*FF gates
#define NOUTD 64
#define KARY 8
#define NPERMS 4
#define PARTITIONABLE 1
#define TILE 128
#define NTILES ((NN + TILE - 1) / TILE)   // 782
#define LTHREADS 512

// ---- packed f32x2 helpers (xw_kernel) ----
#define FMA2(d, a, b, c) asm("fma.rn.f32x2 %0, %1, %2, %3;" : "=l"(d) : "l"(a), "l"(b), "l"(c))
#define PACK2(out, lo, hi)  asm("mov.b64 %0, {%1, %2};" : "=l"(out) : "f"(lo), "f"(hi))

// ------------------------- scratch -------------------------
__device__ float d_XW[NN * (size_t)GG];
__device__ float d_hneigh[NN * (size_t)FF];
__device__ float d_WtIH[FF * GG];
__device__ float d_bcat[GG];
__device__ uint32_t d_Bpack[GG * FF / 2];   // Whh bf16x2, m16n8k16 fragment-packed (128KB)
__device__ int d_deg[NN];
__device__ int d_off[NN + 1];
__device__ int d_cur[NN];
__device__ int d_csr[EE];
__device__ unsigned d_ubits[EE];
__device__ int d_nbrT[KARY * NN];
__device__ int d_len[NN];

// ------------------------- mma.sync helpers (sm_80+ baseline) -------------------------
__device__ __forceinline__ uint32_t smem_u32(const void* p) {
    uint32_t a;
    asm("{ .reg .u64 t; cvta.to.shared.u64 t, %1; cvt.u32.u64 %0, t; }" : "=r"(a) : "l"(p));
    return a;
}
// pack {lo, hi} floats -> bf16x2 (lo in low 16 bits)
__device__ __forceinline__ uint32_t pack_bf16x2(float lo, float hi) {
    uint32_t d;
    asm("cvt.rn.bf16x2.f32 %0, %1, %2;" : "=r"(d) : "f"(hi), "f"(lo));
    return d;
}
#define MMAB(d, a, bb0, bb1) asm volatile( \
    "mma.sync.aligned.m16n8k16.row.col.f32.bf16.bf16.f32 {%0,%1,%2,%3}, {%4,%5,%6,%7}, {%8,%9}, {%0,%1,%2,%3};" \
    : "+f"((d)[0]), "+f"((d)[1]), "+f"((d)[2]), "+f"((d)[3]) \
    : "r"((a).x), "r"((a).y), "r"((a).z), "r"((a).w), "r"(bb0), "r"(bb1))

__device__ __forceinline__ void cp16(uint32_t s, const void* g) {
    asm volatile("cp.async.cg.shared.global [%0], [%1], 16;" :: "r"(s), "l"(g));
}
#define CP_COMMIT() asm volatile("cp.async.commit_group;")
#define CP_WAIT(N)  asm volatile("cp.async.wait_group %0;" :: "n"(N))

// ------------------------- threefry2x32-20 -------------------------
__device__ __forceinline__ uint32_t rotl32(uint32_t v, int d) { return (v << d) | (v >> (32 - d)); }
__device__ __forceinline__ void threefry2x32(uint32_t k0, uint32_t k1,
                                             uint32_t x0, uint32_t x1,
                                             uint32_t& o0, uint32_t& o1) {
    uint32_t ks2 = k0 ^ k1 ^ 0x1BD11BDAu;
    x0 += k0; x1 += k1;
#define TF_R(r) { x0 += x1; x1 = rotl32(x1, r); x1 ^= x0; }
    TF_R(13) TF_R(15) TF_R(26) TF_R(6)   x0 += k1;  x1 += ks2 + 1u;
    TF_R(17) TF_R(29) TF_R(16) TF_R(24)  x0 += ks2; x1 += k0 + 2u;
    TF_R(13) TF_R(15) TF_R(26) TF_R(6)   x0 += k0;  x1 += k1 + 3u;
    TF_R(17) TF_R(29) TF_R(16) TF_R(24)  x0 += k1;  x1 += ks2 + 4u;
    TF_R(13) TF_R(15) TF_R(26) TF_R(6)   x0 += ks2; x1 += k0 + 5u;
#undef TF_R
    o0 = x0; o1 = x1;
}

__device__ __forceinline__ float sigf(float x) { return __fdividef(1.f, 1.f + __expf(-x)); }
__device__ __forceinline__ float tanhf_fast(float x) {
    float ax = fabsf(x);
    float e = __expf(-2.f * ax);
    float t = (1.f - e) * __fdividef(1.f, 1.f + e);
    return copysignf(t, x);
}

// ------------------------- setup kernels -------------------------
__global__ void zero_pre_kernel() {
    for (int i = blockIdx.x * blockDim.x + threadIdx.x; i < NN * FF; i += gridDim.x * blockDim.x) {
        d_hneigh[i] = 0.f;
        if (i < NN) d_deg[i] = 0;
    }
}

__global__ void deg_kernel(const int* __restrict__ adj) {
    int e = blockIdx.x * blockDim.x + threadIdx.x;
    if (e >= EE) return;
    atomicAdd(&d_deg[adj[2 * e]], 1);
}

__global__ void scan_kernel() {
    __shared__ int sh[32];
    int tid = threadIdx.x;
    unsigned lane = tid & 31, wid = tid >> 5;
    int carry = 0;
    for (int base = 0; base < NN; base += 1024) {
        int i = base + tid;
        int v = (i < NN) ? d_deg[i] : 0;
        int x = v;
        #pragma unroll
        for (int s = 1; s < 32; s <<= 1) {
            int y = __shfl_up_sync(0xFFFFFFFFu, x, s);
            if (lane >= s) x += y;
        }
        if (lane == 31) sh[wid] = x;
        __syncthreads();
        if (wid == 0) {
            int y2 = sh[lane];
            #pragma unroll
            for (int s = 1; s < 32; s <<= 1) {
                int z = __shfl_up_sync(0xFFFFFFFFu, y2, s);
                if (lane >= s) y2 += z;
            }
            sh[lane] = y2;
        }
        __syncthreads();
        int wpre = (wid == 0) ? 0 : sh[wid - 1];
        int incl = wpre + x;
        if (i < NN) { d_off[i] = carry + incl - v; d_cur[i] = carry + incl - v; }
        int tot = sh[31];
        __syncthreads();
        carry += tot;
    }
    if (tid == 0) d_off[NN] = carry;
}

__global__ void fill_kernel(const int* __restrict__ adj) {
    int e = blockIdx.x * blockDim.x + threadIdx.x;
    if (e >= EE) return;
    int s = adj[2 * e];
    int pos = atomicAdd(&d_cur[s], 1);
    d_csr[pos] = e;
}

__global__ void trans_kernel(const float* __restrict__ w_ih,
                             const float* __restrict__ b_ih, const float* __restrict__ b_hh) {
    int idx = blockIdx.x * blockDim.x + threadIdx.x;
    if (idx < FF * GG) {
        int j = idx / FF, k = idx % FF;
        d_WtIH[k * GG + j] = w_ih[idx];
    }
    if (idx < GG) d_bcat[idx] = b_ih[idx] + b_hh[idx];
}

// Whh (512,128) -> bf16x2 m16n8k16 B fragments:
// word = (((c*4+wn)*8 + i)*32 + lane)*8 + nt*2 + br
// gate = c*128 + wn*32 + nt*8 + lane/4 ; k0 = i*16 + (lane%4)*2 + br*8
// value = bf16x2(Whh[gate][k0], Whh[gate][k0+1])  (lo = k0)
__global__ void bpack_kernel(const float* __restrict__ w_hh) {
    int wdx = blockIdx.x * blockDim.x + threadIdx.x;
    if (wdx >= GG * FF / 2) return;
    int br = wdx & 1, nt = (wdx >> 1) & 3, lane = (wdx >> 3) & 31;
    int i = (wdx >> 8) & 7, cw = wdx >> 11;
    int wn = cw & 3, c = cw >> 2;
    int gate = c * 128 + wn * 32 + nt * 8 + (lane >> 2);
    int k0 = i * 16 + (lane & 3) * 2 + br * 8;
    d_Bpack[wdx] = pack_bf16x2(w_hh[gate * FF + k0], w_hh[gate * FF + k0 + 1]);
}

// ------------------------- per-perm kernels -------------------------
__global__ void rng_kernel(int p) {
    int e = blockIdx.x * blockDim.x + threadIdx.x;
    if (e >= EE) return;
    uint32_t ka, kb;
    threefry2x32(0u, 42u, 0u, (uint32_t)p, ka, kb);
    uint32_t o0, o1, bits;
#if PARTITIONABLE
    threefry2x32(ka, kb, 0u, (uint32_t)e, o0, o1);
    bits = o0 ^ o1;
#else
    const int H = EE / 2;
    if (e < H) { threefry2x32(ka, kb, (uint32_t)e, (uint32_t)(e + H), o0, o1); bits = o0; }
    else       { threefry2x32(ka, kb, (uint32_t)(e - H), (uint32_t)e, o0, o1); bits = o1; }
#endif
    d_ubits[e] = bits >> 9;
}

__global__ void select_kernel(const int* __restrict__ adj) {
    int n = blockIdx.x * blockDim.x + threadIdx.x;
    if (n >= NN) return;
    int off = d_off[n];
    int d = d_deg[n];
    unsigned long long k8[KARY];
    int dst8[KARY];
    #pragma unroll
    for (int i = 0; i < KARY; i++) { k8[i] = ~0ull; dst8[i] = 0; }
    for (int ii = 0; ii < d; ii++) {
        int e = d_csr[off + ii];
        unsigned long long key = ((unsigned long long)d_ubits[e] << 21) | (unsigned)e;
        int dv = adj[2 * e + 1];
        if (key < k8[KARY - 1]) {
            #pragma unroll
            for (int s = 0; s < KARY; s++) {
                if (key < k8[s]) {
                    unsigned long long tk = k8[s]; k8[s] = key; key = tk;
                    int td = dst8[s]; dst8[s] = dv; dv = td;
                }
            }
        }
    }
    int ln = d < KARY ? d : KARY;
    d_len[n] = ln;
    #pragma unroll
    for (int t = 0; t < KARY; t++) d_nbrT[t * NN + n] = (t < ln) ? dst8[t] : 0;
}

// ------------------------- GEMM: XW = node_feat @ w_ih^T (fp32 FFMA2) -------------------------
__global__ __launch_bounds__(512, 1) void xw_kernel(const float* __restrict__ nf) {
    __shared__ __align__(16) float As[8 * 68];
    __shared__ __align__(16) float Bs[8 * 512];
    int tid = threadIdx.x;
    int base = blockIdx.x * 64;
    int ns = tid & 15, js = tid >> 4;
    unsigned long long acc2[4][8];
    #pragma unroll
    for (int i = 0; i < 4; i++)
        #pragma unroll
        for (int jv = 0; jv < 8; jv++) acc2[i][jv] = 0ull;

    for (int kb = 0; kb < FF; kb += 8) {
        int n_l = tid >> 3, kk = tid & 7;
        int n = base + n_l;
        As[kk * 68 + n_l] = (n < NN) ? nf[(size_t)n * FF + kb + kk] : 0.f;
        const float4* Bg = (const float4*)(d_WtIH + kb * GG);
        ((float4*)Bs)[tid] = Bg[tid];
        ((float4*)Bs)[tid + 512] = Bg[tid + 512];
        __syncthreads();
        #pragma unroll
        for (int k2 = 0; k2 < 8; ++k2) {
            float4 a = *(const float4*)&As[k2 * 68 + ns * 4];
            unsigned long long ap[4];
            PACK2(ap[0], a.x, a.x); PACK2(ap[1], a.y, a.y);
            PACK2(ap[2], a.z, a.z); PACK2(ap[3], a.w, a.w);
            #pragma unroll
            for (int q = 0; q < 4; ++q) {
                ulonglong2 b2 = *(const ulonglong2*)&Bs[k2 * 512 + q * 128 + js * 4];
                #pragma unroll
                for (int i = 0; i < 4; i++) {
                    FMA2(acc2[i][q * 2 + 0], ap[i], b2.x, acc2[i][q * 2 + 0]);
                    FMA2(acc2[i][q * 2 + 1], ap[i], b2.y, acc2[i][q * 2 + 1]);
                }
            }
        }
        __syncthreads();
    }
    #pragma unroll
    for (int i = 0; i < 4; i++) {
        int n = base + ns * 4 + i;
        if (n >= NN) continue;
        #pragma unroll
        for (int q = 0; q < 4; q++) {
            ulonglong2 r;
            r.x = acc2[i][q * 2 + 0];
            r.y = acc2[i][q * 2 + 1];
            *(ulonglong2*)&d_XW[(size_t)n * GG + q * 128 + js * 4] = r;
        }
    }
}

// ---- persistent per-tile LSTM: all 8 steps, bf16 mma.sync, Whh RESIDENT in SMEM ----
// 512 threads = 16 warps: wm 0..3 (M=32: 2 m16 tiles) x wn 0..3 (N=32: 4 n8 tiles).
// SMEM: A-pack (h bf16 frags) 32KB | B resident (Whh bf16 frags) 128KB. 2 barriers/step.
__global__ __launch_bounds__(LTHREADS, 1) void lstm_perm_kernel() {
    extern __shared__ __align__(16) uint32_t smw[];
    uint32_t sbase = smem_u32(smw);
    uint32_t* smA = smw;                 // 8192 words
    uint32_t* smB = smw + 8192;          // 32768 words
    const int tid = threadIdx.x, lane = tid & 31, w = tid >> 5;
    const int wm = w >> 2, wn = w & 3;
    const int base = blockIdx.x * TILE;
    const int qb = 2 * (lane & 3);           // feat pair base within n-tile

    int glen[4];
    #pragma unroll
    for (int mt = 0; mt < 2; mt++)
        #pragma unroll
        for (int s = 0; s < 2; s++) {
            int g = base + wm * 32 + mt * 16 + (lane >> 2) + s * 8;
            glen[mt * 2 + s] = (g < NN) ? d_len[g] : 0;
        }

    float c_[32], sigi[32];
    #pragma unroll
    for (int i = 0; i < 32; i++) c_[i] = 0.f;

    // one-time: load resident B (128KB) via cp.async; zero A-pack (h=0)
    {
        const uint4* src = (const uint4*)d_Bpack;
        uint32_t dst = sbase + 8192u * 4u;
        #pragma unroll
        for (int it = 0; it < 16; it++)
            cp16(dst + (uint32_t)(it * LTHREADS + tid) * 16u, src + it * LTHREADS + tid);
        CP_COMMIT();
    }
    for (int i = tid; i < 8192; i += LTHREADS) smA[i] = 0u;
    CP_WAIT(0);

    for (int t = 0; t < KARY; t++) {
        __syncthreads();   // h stores (or init) visible to all mma reads

        int nb[4];
        #pragma unroll
        for (int e = 0; e < 4; e++) {
            int g = base + wm * 32 + (e >> 1) * 16 + (lane >> 2) + (e & 1) * 8;
            nb[e] = (g < NN) ? d_nbrT[t * NN + g] : 0;
        }

        #pragma unroll
        for (int c = 0; c < 4; c++) {
            float acc[32];
            #pragma unroll
            for (int i = 0; i < 32; i++) acc[i] = 0.f;

            if (t > 0) {
                const uint32_t* Bc = smB + (c * 4 + wn) * 2048;
                #pragma unroll
                for (int i = 0; i < 8; i++) {
                    uint4 a[2];
                    #pragma unroll
                    for (int mt = 0; mt < 2; mt++)
                        a[mt] = *(const uint4*)(smA + (((wm * 2 + mt) * 8 + i) * 32 + lane) * 4);
                    const uint32_t* bp = Bc + i * 256 + lane * 8;
                    uint4 b0 = *(const uint4*)bp;
                    uint4 b1 = *(const uint4*)(bp + 4);
                    #pragma unroll
                    for (int mt = 0; mt < 2; mt++) {
                        MMAB(&acc[mt * 16 + 0],  a[mt], b0.x, b0.y);
                        MMAB(&acc[mt * 16 + 4],  a[mt], b0.z, b0.w);
                        MMAB(&acc[mt * 16 + 8],  a[mt], b1.x, b1.y);
                        MMAB(&acc[mt * 16 + 12], a[mt], b1.z, b1.w);
                    }
                }
            }

            // Before the c==3 h-store: every warp reaching this barrier has finished
            // ALL its chunk mma A-reads (chunks are sequential per warp), so the
            // store cannot race any read.
            if (c == 3) __syncthreads();

            // ---- epilogue for gate-group c ----
            float2 bv[4];
            #pragma unroll
            for (int nt = 0; nt < 4; nt++)
                bv[nt] = *(const float2*)&d_bcat[c * 128 + wn * 32 + nt * 8 + qb];
            #pragma unroll
            for (int mt = 0; mt < 2; mt++)
                #pragma unroll
                for (int s = 0; s < 2; s++) {
                    int e = mt * 2 + s;
                    bool act = (t < glen[e]);
                    const float* xr = d_XW + (size_t)nb[e] * GG + c * 128 + wn * 32;
                    #pragma unroll
                    for (int nt = 0; nt < 4; nt++) {
                        float2 xv = *(const float2*)&xr[nt * 8 + qb];
                        int i0 = mt * 16 + nt * 4 + s * 2;
                        float p0 = acc[i0] + xv.x + bv[nt].x;
                        float p1 = acc[i0 + 1] + xv.y + bv[nt].y;
                        if (c == 0) {
                            sigi[i0] = sigf(p0);
                            sigi[i0 + 1] = sigf(p1);
                        } else if (c == 1) {
                            if (act) { c_[i0] *= sigf(p0); c_[i0 + 1] *= sigf(p1); }
                        } else if (c == 2) {
                            if (act) {
                                c_[i0]     = fmaf(sigi[i0],     tanhf_fast(p0), c_[i0]);
                                c_[i0 + 1] = fmaf(sigi[i0 + 1], tanhf_fast(p1), c_[i0 + 1]);
                            }
                        } else {
                            if (act) {
                                float h0 = sigf(p0) * tanhf_fast(c_[i0]);
                                float h1 = sigf(p1) * tanhf_fast(c_[i0 + 1]);
                                // h -> A-pack bf16 fragment; {f, f+1} = one bf16x2 word,
                                // producer lane == consumer lane.
                                int addr = (((wm * 2 + mt) * 8 + (wn * 2 + (nt >> 1))) * 32
                                            + lane) * 4 + s + 2 * (nt & 1);
                                smA[addr] = pack_bf16x2(h0, h1);
                            }
                        }
                    }
                }
        }
    }

    // ---- writeback: hneigh += c (disjoint ownership, no atomics) ----
    #pragma unroll
    for (int mt = 0; mt < 2; mt++)
        #pragma unroll
        for (int s = 0; s < 2; s++) {
            int g = base + wm * 32 + mt * 16 + (lane >> 2) + s * 8;
            if (g >= NN) continue;
            #pragma unroll
            for (int nt = 0; nt < 4; nt++) {
                int i0 = mt * 16 + nt * 4 + s * 2;
                float2* hp = (float2*)&d_hneigh[(size_t)g * FF + wn * 32 + nt * 8 + qb];
                float2 v = *hp;
                v.x += c_[i0];
                v.y += c_[i0 + 1];
                *hp = v;
            }
        }
}

// ------------------------- output layer -------------------------
__global__ __launch_bounds__(512) void out_kernel(const float* __restrict__ nf,
                                                  const float* __restrict__ w,
                                                  const float* __restrict__ bias,
                                                  float* __restrict__ out) {
    int base = blockIdx.x * 64;
    int o = threadIdx.x & 63;
    int ng = threadIdx.x >> 6;
    for (int g = 0; g < 8; ++g) {
        int n = base + g * 8 + ng;
        if (n >= NN) continue;
        float z = bias[o];
        const float* nfr = nf + (size_t)n * FF;
        const float* hr = d_hneigh + (size_t)n * FF;
        #pragma unroll 4
        for (int k = 0; k < FF; k++) z = fmaf(nfr[k], w[k * NOUTD + o], z);
        #pragma unroll 4
        for (int k = 0; k < FF; k++) z = fmaf(0.25f * hr[k], w[(FF + k) * NOUTD + o], z);
        out[(size_t)n * NOUTD + o] = 1.f / (1.f + __expf(-z));
    }
}

// ------------------------- launch -------------------------
extern "C" void kernel_launch(void* const* d_in, const int* in_sizes, int n_in,
                              void* d_out, int out_size) {
    const float* node_feat = (const float*)d_in[0];
    const int*   adj       = (const int*)d_in[1];
    const float* w_ih      = (const float*)d_in[2];
    const float* w_hh      = (const float*)d_in[3];
    const float* b_ih      = (const float*)d_in[4];
    const float* b_hh      = (const float*)d_in[5];
    const float* weight    = (const float*)d_in[6];
    const float* bias      = (const float*)d_in[7];
    float* out = (float*)d_out;

    const int EB = (EE + 255) / 256;
    const int NB64 = (NN + 63) / 64;
    const int SMEM_LSTM = (8192 + 32768) * 4;   // A-pack 32KB + resident B 128KB

    cudaFuncSetAttribute(lstm_perm_kernel, cudaFuncAttributeMaxDynamicSharedMemorySize, SMEM_LSTM);

    zero_pre_kernel<<<2048, 256>>>();
    deg_kernel<<<EB, 256>>>(adj);
    scan_kernel<<<1, 1024>>>();
    fill_kernel<<<EB, 256>>>(adj);
    trans_kernel<<<(FF * GG + 511) / 512, 512>>>(w_ih, b_ih, b_hh);
    bpack_kernel<<<(GG * FF / 2 + 255) / 256, 256>>>(w_hh);
    xw_kernel<<<NB64, 512>>>(node_feat);

    for (int p = 0; p < NPERMS; p++) {
        rng_kernel<<<EB, 256>>>(p);
        select_kernel<<<(NN + 255) / 256, 256>>>(adj);
        lstm_perm_kernel<<<NTILES, LTHREADS, SMEM_LSTM>>>();
    }
    out_kernel<<<NB64, 512>>>(node_feat, weight, bias, out);
}

// round 17
// speedup vs baseline: 3.0663x; 1.0688x over previous
#include <cuda_runtime.h>
#include <cuda_fp16.h>
#include <cstdint>

#define NN 100000
#define FF 128
#define EE 1600000
#define GG 512          // 4*FF gates
#define NOUTD 64
#define KARY 8
#define NPERMS 4
#define PARTITIONABLE 1
#define TILE 128
#define NTILES ((NN + TILE - 1) / TILE)   // 782
#define LTHREADS 512

// ---- packed f32x2 helpers (xw_kernel) ----
#define FMA2(d, a, b, c) asm("fma.rn.f32x2 %0, %1, %2, %3;" : "=l"(d) : "l"(a), "l"(b), "l"(c))
#define PACK2(out, lo, hi)  asm("mov.b64 %0, {%1, %2};" : "=l"(out) : "f"(lo), "f"(hi))
#define UNPACK2(lo, hi, in) asm("mov.b64 {%0, %1}, %2;" : "=f"(lo), "=f"(hi) : "l"(in))

// ------------------------- scratch -------------------------
__device__ uint32_t d_XWh[NN * (size_t)(GG / 2)];  // XW as half2 (100MB): halves gather DRAM traffic
__device__ float d_hneigh[NN * (size_t)FF];
__device__ float d_WtIH[FF * GG];
__device__ float d_bcat[GG];
__device__ uint32_t d_Bpack[GG * FF / 2];   // Whh bf16x2, m16n8k16 fragment-packed (128KB)
__device__ int d_deg[NN];
__device__ int d_off[NN + 1];
__device__ int d_cur[NN];
__device__ int d_csr[EE];
__device__ unsigned d_ubits[EE];
__device__ int d_nbrT[KARY * NN];
__device__ int d_len[NN];

// ------------------------- mma.sync helpers (sm_80+ baseline) -------------------------
__device__ __forceinline__ uint32_t smem_u32(const void* p) {
    uint32_t a;
    asm("{ .reg .u64 t; cvta.to.shared.u64 t, %1; cvt.u32.u64 %0, t; }" : "=r"(a) : "l"(p));
    return a;
}
// pack {lo, hi} floats -> bf16x2 (lo in low 16 bits)
__device__ __forceinline__ uint32_t pack_bf16x2(float lo, float hi) {
    uint32_t d;
    asm("cvt.rn.bf16x2.f32 %0, %1, %2;" : "=r"(d) : "f"(hi), "f"(lo));
    return d;
}
// pack {lo, hi} floats -> f16x2 (lo in low 16 bits)
__device__ __forceinline__ uint32_t pack_f16x2(float lo, float hi) {
    uint32_t d;
    asm("cvt.rn.f16x2.f32 %0, %1, %2;" : "=r"(d) : "f"(hi), "f"(lo));
    return d;
}
#define MMAB(d, a, bb0, bb1) asm volatile( \
    "mma.sync.aligned.m16n8k16.row.col.f32.bf16.bf16.f32 {%0,%1,%2,%3}, {%4,%5,%6,%7}, {%8,%9}, {%0,%1,%2,%3};" \
    : "+f"((d)[0]), "+f"((d)[1]), "+f"((d)[2]), "+f"((d)[3]) \
    : "r"((a).x), "r"((a).y), "r"((a).z), "r"((a).w), "r"(bb0), "r"(bb1))

__device__ __forceinline__ void cp16(uint32_t s, const void* g) {
    asm volatile("cp.async.cg.shared.global [%0], [%1], 16;" :: "r"(s), "l"(g));
}
#define CP_COMMIT() asm volatile("cp.async.commit_group;")
#define CP_WAIT(N)  asm volatile("cp.async.wait_group %0;" :: "n"(N))

// ------------------------- threefry2x32-20 -------------------------
__device__ __forceinline__ uint32_t rotl32(uint32_t v, int d) { return (v << d) | (v >> (32 - d)); }
__device__ __forceinline__ void threefry2x32(uint32_t k0, uint32_t k1,
                                             uint32_t x0, uint32_t x1,
                                             uint32_t& o0, uint32_t& o1) {
    uint32_t ks2 = k0 ^ k1 ^ 0x1BD11BDAu;
    x0 += k0; x1 += k1;
#define TF_R(r) { x0 += x1; x1 = rotl32(x1, r); x1 ^= x0; }
    TF_R(13) TF_R(15) TF_R(26) TF_R(6)   x0 += k1;  x1 += ks2 + 1u;
    TF_R(17) TF_R(29) TF_R(16) TF_R(24)  x0 += ks2; x1 += k0 + 2u;
    TF_R(13) TF_R(15) TF_R(26) TF_R(6)   x0 += k0;  x1 += k1 + 3u;
    TF_R(17) TF_R(29) TF_R(16) TF_R(24)  x0 += k1;  x1 += ks2 + 4u;
    TF_R(13) TF_R(15) TF_R(26) TF_R(6)   x0 += ks2; x1 += k0 + 5u;
#undef TF_R
    o0 = x0; o1 = x1;
}

__device__ __forceinline__ float sigf(float x) { return __fdividef(1.f, 1.f + __expf(-x)); }
__device__ __forceinline__ float tanhf_fast(float x) {
    float ax = fabsf(x);
    float e = __expf(-2.f * ax);
    float t = (1.f - e) * __fdividef(1.f, 1.f + e);
    return copysignf(t, x);
}

// ------------------------- setup kernels -------------------------
__global__ void zero_pre_kernel() {
    for (int i = blockIdx.x * blockDim.x + threadIdx.x; i < NN * FF; i += gridDim.x * blockDim.x) {
        d_hneigh[i] = 0.f;
        if (i < NN) d_deg[i] = 0;
    }
}

__global__ void deg_kernel(const int* __restrict__ adj) {
    int e = blockIdx.x * blockDim.x + threadIdx.x;
    if (e >= EE) return;
    atomicAdd(&d_deg[adj[2 * e]], 1);
}

__global__ void scan_kernel() {
    __shared__ int sh[32];
    int tid = threadIdx.x;
    unsigned lane = tid & 31, wid = tid >> 5;
    int carry = 0;
    for (int base = 0; base < NN; base += 1024) {
        int i = base + tid;
        int v = (i < NN) ? d_deg[i] : 0;
        int x = v;
        #pragma unroll
        for (int s = 1; s < 32; s <<= 1) {
            int y = __shfl_up_sync(0xFFFFFFFFu, x, s);
            if (lane >= s) x += y;
        }
        if (lane == 31) sh[wid] = x;
        __syncthreads();
        if (wid == 0) {
            int y2 = sh[lane];
            #pragma unroll
            for (int s = 1; s < 32; s <<= 1) {
                int z = __shfl_up_sync(0xFFFFFFFFu, y2, s);
                if (lane >= s) y2 += z;
            }
            sh[lane] = y2;
        }
        __syncthreads();
        int wpre = (wid == 0) ? 0 : sh[wid - 1];
        int incl = wpre + x;
        if (i < NN) { d_off[i] = carry + incl - v; d_cur[i] = carry + incl - v; }
        int tot = sh[31];
        __syncthreads();
        carry += tot;
    }
    if (tid == 0) d_off[NN] = carry;
}

__global__ void fill_kernel(const int* __restrict__ adj) {
    int e = blockIdx.x * blockDim.x + threadIdx.x;
    if (e >= EE) return;
    int s = adj[2 * e];
    int pos = atomicAdd(&d_cur[s], 1);
    d_csr[pos] = e;
}

__global__ void trans_kernel(const float* __restrict__ w_ih,
                             const float* __restrict__ b_ih, const float* __restrict__ b_hh) {
    int idx = blockIdx.x * blockDim.x + threadIdx.x;
    if (idx < FF * GG) {
        int j = idx / FF, k = idx % FF;
        d_WtIH[k * GG + j] = w_ih[idx];
    }
    if (idx < GG) d_bcat[idx] = b_ih[idx] + b_hh[idx];
}

// Whh (512,128) -> bf16x2 m16n8k16 B fragments:
// word = (((c*4+wn)*8 + i)*32 + lane)*8 + nt*2 + br
// gate = c*128 + wn*32 + nt*8 + lane/4 ; k0 = i*16 + (lane%4)*2 + br*8
__global__ void bpack_kernel(const float* __restrict__ w_hh) {
    int wdx = blockIdx.x * blockDim.x + threadIdx.x;
    if (wdx >= GG * FF / 2) return;
    int br = wdx & 1, nt = (wdx >> 1) & 3, lane = (wdx >> 3) & 31;
    int i = (wdx >> 8) & 7, cw = wdx >> 11;
    int wn = cw & 3, c = cw >> 2;
    int gate = c * 128 + wn * 32 + nt * 8 + (lane >> 2);
    int k0 = i * 16 + (lane & 3) * 2 + br * 8;
    d_Bpack[wdx] = pack_bf16x2(w_hh[gate * FF + k0], w_hh[gate * FF + k0 + 1]);
}

// ------------------------- per-perm kernels -------------------------
__global__ void rng_kernel(int p) {
    int e = blockIdx.x * blockDim.x + threadIdx.x;
    if (e >= EE) return;
    uint32_t ka, kb;
    threefry2x32(0u, 42u, 0u, (uint32_t)p, ka, kb);
    uint32_t o0, o1, bits;
#if PARTITIONABLE
    threefry2x32(ka, kb, 0u, (uint32_t)e, o0, o1);
    bits = o0 ^ o1;
#else
    const int H = EE / 2;
    if (e < H) { threefry2x32(ka, kb, (uint32_t)e, (uint32_t)(e + H), o0, o1); bits = o0; }
    else       { threefry2x32(ka, kb, (uint32_t)(e - H), (uint32_t)e, o0, o1); bits = o1; }
#endif
    d_ubits[e] = bits >> 9;
}

__global__ void select_kernel(const int* __restrict__ adj) {
    int n = blockIdx.x * blockDim.x + threadIdx.x;
    if (n >= NN) return;
    int off = d_off[n];
    int d = d_deg[n];
    unsigned long long k8[KARY];
    int dst8[KARY];
    #pragma unroll
    for (int i = 0; i < KARY; i++) { k8[i] = ~0ull; dst8[i] = 0; }
    for (int ii = 0; ii < d; ii++) {
        int e = d_csr[off + ii];
        unsigned long long key = ((unsigned long long)d_ubits[e] << 21) | (unsigned)e;
        int dv = adj[2 * e + 1];
        if (key < k8[KARY - 1]) {
            #pragma unroll
            for (int s = 0; s < KARY; s++) {
                if (key < k8[s]) {
                    unsigned long long tk = k8[s]; k8[s] = key; key = tk;
                    int td = dst8[s]; dst8[s] = dv; dv = td;
                }
            }
        }
    }
    int ln = d < KARY ? d : KARY;
    d_len[n] = ln;
    #pragma unroll
    for (int t = 0; t < KARY; t++) d_nbrT[t * NN + n] = (t < ln) ? dst8[t] : 0;
}

// ------------------------- GEMM: XW = node_feat @ w_ih^T (fp32 FFMA2; fp16 store) -------------------------
__global__ __launch_bounds__(512, 1) void xw_kernel(const float* __restrict__ nf) {
    __shared__ __align__(16) float As[8 * 68];
    __shared__ __align__(16) float Bs[8 * 512];
    int tid = threadIdx.x;
    int base = blockIdx.x * 64;
    int ns = tid & 15, js = tid >> 4;
    unsigned long long acc2[4][8];
    #pragma unroll
    for (int i = 0; i < 4; i++)
        #pragma unroll
        for (int jv = 0; jv < 8; jv++) acc2[i][jv] = 0ull;

    for (int kb = 0; kb < FF; kb += 8) {
        int n_l = tid >> 3, kk = tid & 7;
        int n = base + n_l;
        As[kk * 68 + n_l] = (n < NN) ? nf[(size_t)n * FF + kb + kk] : 0.f;
        const float4* Bg = (const float4*)(d_WtIH + kb * GG);
        ((float4*)Bs)[tid] = Bg[tid];
        ((float4*)Bs)[tid + 512] = Bg[tid + 512];
        __syncthreads();
        #pragma unroll
        for (int k2 = 0; k2 < 8; ++k2) {
            float4 a = *(const float4*)&As[k2 * 68 + ns * 4];
            unsigned long long ap[4];
            PACK2(ap[0], a.x, a.x); PACK2(ap[1], a.y, a.y);
            PACK2(ap[2], a.z, a.z); PACK2(ap[3], a.w, a.w);
            #pragma unroll
            for (int q = 0; q < 4; ++q) {
                ulonglong2 b2 = *(const ulonglong2*)&Bs[k2 * 512 + q * 128 + js * 4];
                #pragma unroll
                for (int i = 0; i < 4; i++) {
                    FMA2(acc2[i][q * 2 + 0], ap[i], b2.x, acc2[i][q * 2 + 0]);
                    FMA2(acc2[i][q * 2 + 1], ap[i], b2.y, acc2[i][q * 2 + 1]);
                }
            }
        }
        __syncthreads();
    }
    #pragma unroll
    for (int i = 0; i < 4; i++) {
        int n = base + ns * 4 + i;
        if (n >= NN) continue;
        #pragma unroll
        for (int q = 0; q < 4; q++) {
            float f0, f1, f2, f3;
            UNPACK2(f0, f1, acc2[i][q * 2 + 0]);
            UNPACK2(f2, f3, acc2[i][q * 2 + 1]);
            uint2 r;
            r.x = pack_f16x2(f0, f1);
            r.y = pack_f16x2(f2, f3);
            *(uint2*)&d_XWh[(size_t)n * (GG / 2) + q * 64 + js * 2] = r;
        }
    }
}

// ---- persistent per-tile LSTM: all 8 steps, bf16 mma.sync, Whh RESIDENT in SMEM ----
// 512 threads = 16 warps: wm 0..3 (M=32: 2 m16 tiles) x wn 0..3 (N=32: 4 n8 tiles).
// SMEM: A-pack (h bf16 frags) 32KB | B resident (Whh bf16 frags) 128KB. 2 barriers/step.
// XW gathered as half2 (halved DRAM traffic; 100MB working set ~ L2-sized).
__global__ __launch_bounds__(LTHREADS, 1) void lstm_perm_kernel() {
    extern __shared__ __align__(16) uint32_t smw[];
    uint32_t sbase = smem_u32(smw);
    uint32_t* smA = smw;                 // 8192 words
    uint32_t* smB = smw + 8192;          // 32768 words
    const int tid = threadIdx.x, lane = tid & 31, w = tid >> 5;
    const int wm = w >> 2, wn = w & 3;
    const int base = blockIdx.x * TILE;
    const int qb = 2 * (lane & 3);           // feat pair base within n-tile

    int glen[4];
    #pragma unroll
    for (int mt = 0; mt < 2; mt++)
        #pragma unroll
        for (int s = 0; s < 2; s++) {
            int g = base + wm * 32 + mt * 16 + (lane >> 2) + s * 8;
            glen[mt * 2 + s] = (g < NN) ? d_len[g] : 0;
        }

    float c_[32], sigi[32];
    #pragma unroll
    for (int i = 0; i < 32; i++) c_[i] = 0.f;

    // one-time: load resident B (128KB) via cp.async; zero A-pack (h=0)
    {
        const uint4* src = (const uint4*)d_Bpack;
        uint32_t dst = sbase + 8192u * 4u;
        #pragma unroll
        for (int it = 0; it < 16; it++)
            cp16(dst + (uint32_t)(it * LTHREADS + tid) * 16u, src + it * LTHREADS + tid);
        CP_COMMIT();
    }
    for (int i = tid; i < 8192; i += LTHREADS) smA[i] = 0u;
    CP_WAIT(0);

    for (int t = 0; t < KARY; t++) {
        __syncthreads();   // h stores (or init) visible to all mma reads

        int nb[4];
        #pragma unroll
        for (int e = 0; e < 4; e++) {
            int g = base + wm * 32 + (e >> 1) * 16 + (lane >> 2) + (e & 1) * 8;
            nb[e] = (g < NN) ? d_nbrT[t * NN + g] : 0;
        }

        #pragma unroll
        for (int c = 0; c < 4; c++) {
            float acc[32];
            #pragma unroll
            for (int i = 0; i < 32; i++) acc[i] = 0.f;

            if (t > 0) {
                const uint32_t* Bc = smB + (c * 4 + wn) * 2048;
                #pragma unroll
                for (int i = 0; i < 8; i++) {
                    uint4 a[2];
                    #pragma unroll
                    for (int mt = 0; mt < 2; mt++)
                        a[mt] = *(const uint4*)(smA + (((wm * 2 + mt) * 8 + i) * 32 + lane) * 4);
                    const uint32_t* bp = Bc + i * 256 + lane * 8;
                    uint4 b0 = *(const uint4*)bp;
                    uint4 b1 = *(const uint4*)(bp + 4);
                    #pragma unroll
                    for (int mt = 0; mt < 2; mt++) {
                        MMAB(&acc[mt * 16 + 0],  a[mt], b0.x, b0.y);
                        MMAB(&acc[mt * 16 + 4],  a[mt], b0.z, b0.w);
                        MMAB(&acc[mt * 16 + 8],  a[mt], b1.x, b1.y);
                        MMAB(&acc[mt * 16 + 12], a[mt], b1.z, b1.w);
                    }
                }
            }

            // Before the c==3 h-store: every warp reaching this barrier has finished
            // ALL its chunk mma A-reads (chunks are sequential per warp), so the
            // store cannot race any read.
            if (c == 3) __syncthreads();

            // ---- epilogue for gate-group c ----
            float2 bv[4];
            #pragma unroll
            for (int nt = 0; nt < 4; nt++)
                bv[nt] = *(const float2*)&d_bcat[c * 128 + wn * 32 + nt * 8 + qb];
            #pragma unroll
            for (int mt = 0; mt < 2; mt++)
                #pragma unroll
                for (int s = 0; s < 2; s++) {
                    int e = mt * 2 + s;
                    bool act = (t < glen[e]);
                    // XW row as half2: base (c*128 + wn*32)/2 = c*64 + wn*16
                    const uint32_t* xr = d_XWh + (size_t)nb[e] * (GG / 2) + c * 64 + wn * 16;
                    #pragma unroll
                    for (int nt = 0; nt < 4; nt++) {
                        uint32_t xw_w = xr[nt * 4 + (lane & 3)];
                        float2 xv = __half22float2(*(const __half2*)&xw_w);
                        int i0 = mt * 16 + nt * 4 + s * 2;
                        float p0 = acc[i0] + xv.x + bv[nt].x;
                        float p1 = acc[i0 + 1] + xv.y + bv[nt].y;
                        if (c == 0) {
                            sigi[i0] = sigf(p0);
                            sigi[i0 + 1] = sigf(p1);
                        } else if (c == 1) {
                            if (act) { c_[i0] *= sigf(p0); c_[i0 + 1] *= sigf(p1); }
                        } else if (c == 2) {
                            if (act) {
                                c_[i0]     = fmaf(sigi[i0],     tanhf_fast(p0), c_[i0]);
                                c_[i0 + 1] = fmaf(sigi[i0 + 1], tanhf_fast(p1), c_[i0 + 1]);
                            }
                        } else {
                            if (act) {
                                float h0 = sigf(p0) * tanhf_fast(c_[i0]);
                                float h1 = sigf(p1) * tanhf_fast(c_[i0 + 1]);
                                // h -> A-pack bf16 fragment; {f, f+1} = one bf16x2 word,
                                // producer lane == consumer lane.
                                int addr = (((wm * 2 + mt) * 8 + (wn * 2 + (nt >> 1))) * 32
                                            + lane) * 4 + s + 2 * (nt & 1);
                                smA[addr] = pack_bf16x2(h0, h1);
                            }
                        }
                    }
                }
        }
    }

    // ---- writeback: hneigh += c (disjoint ownership, no atomics) ----
    #pragma unroll
    for (int mt = 0; mt < 2; mt++)
        #pragma unroll
        for (int s = 0; s < 2; s++) {
            int g = base + wm * 32 + mt * 16 + (lane >> 2) + s * 8;
            if (g >= NN) continue;
            #pragma unroll
            for (int nt = 0; nt < 4; nt++) {
                int i0 = mt * 16 + nt * 4 + s * 2;
                float2* hp = (float2*)&d_hneigh[(size_t)g * FF + wn * 32 + nt * 8 + qb];
                float2 v = *hp;
                v.x += c_[i0];
                v.y += c_[i0 + 1];
                *hp = v;
            }
        }
}

// ------------------------- output layer -------------------------
__global__ __launch_bounds__(512) void out_kernel(const float* __restrict__ nf,
                                                  const float* __restrict__ w,
                                                  const float* __restrict__ bias,
                                                  float* __restrict__ out) {
    int base = blockIdx.x * 64;
    int o = threadIdx.x & 63;
    int ng = threadIdx.x >> 6;
    for (int g = 0; g < 8; ++g) {
        int n = base + g * 8 + ng;
        if (n >= NN) continue;
        float z = bias[o];
        const float* nfr = nf + (size_t)n * FF;
        const float* hr = d_hneigh + (size_t)n * FF;
        #pragma unroll 4
        for (int k = 0; k < FF; k++) z = fmaf(nfr[k], w[k * NOUTD + o], z);
        #pragma unroll 4
        for (int k = 0; k < FF; k++) z = fmaf(0.25f * hr[k], w[(FF + k) * NOUTD + o], z);
        out[(size_t)n * NOUTD + o] = 1.f / (1.f + __expf(-z));
    }
}

// ------------------------- launch -------------------------
extern "C" void kernel_launch(void* const* d_in, const int* in_sizes, int n_in,
                              void* d_out, int out_size) {
    const float* node_feat = (const float*)d_in[0];
    const int*   adj       = (const int*)d_in[1];
    const float* w_ih      = (const float*)d_in[2];
    const float* w_hh      = (const float*)d_in[3];
    const float* b_ih      = (const float*)d_in[4];
    const float* b_hh      = (const float*)d_in[5];
    const float* weight    = (const float*)d_in[6];
    const float* bias      = (const float*)d_in[7];
    float* out = (float*)d_out;

    const int EB = (EE + 255) / 256;
    const int NB64 = (NN + 63) / 64;
    const int SMEM_LSTM = (8192 + 32768) * 4;   // A-pack 32KB + resident B 128KB

    cudaFuncSetAttribute(lstm_perm_kernel, cudaFuncAttributeMaxDynamicSharedMemorySize, SMEM_LSTM);

    zero_pre_kernel<<<2048, 256>>>();
    deg_kernel<<<EB, 256>>>(adj);
    scan_kernel<<<1, 1024>>>();
    fill_kernel<<<EB, 256>>>(adj);
    trans_kernel<<<(FF * GG + 511) / 512, 512>>>(w_ih, b_ih, b_hh);
    bpack_kernel<<<(GG * FF / 2 + 255) / 256, 256>>>(w_hh);
    xw_kernel<<<NB64, 512>>>(node_feat);

    for (int p = 0; p < NPERMS; p++) {
        rng_kernel<<<EB, 256>>>(p);
        select_kernel<<<(NN + 255) / 256, 256>>>(adj);
        lstm_perm_kernel<<<NTILES, LTHREADS, SMEM_LSTM>>>();
    }
    out_kernel<<<NB64, 512>>>(node_feat, weight, bias, out);
}